// round 8
// baseline (speedup 1.0000x reference)
#include <cuda_runtime.h>
#include <stdint.h>
#include <math.h>

// ---------------------------------------------------------------------------
// Problem constants (B=1)
// ---------------------------------------------------------------------------
#define T_SEQ 2048
#define D_MODEL 4096
#define KV_DIM 1024
#define HEAD_DIM 128
#define N_HEADS 32

#define BK 32
#define ROWB 80                 // bytes per fp16 smem row (32 halves + 8 pad)
#define NTHREADS 256
#define STGB 30720              // (128+256) rows * 80 B
#define SMEM_NT (2 * STGB)      // 61440

// AV smem: P 256 rows * 80 = 20480 ; V 32 rows * 272 = 8704
#define VROWB 272
#define AV_STGB (20480 + 8704)  // 29184
#define SMEM_AV (2 * AV_STGB)   // 58368

// ---------------------------------------------------------------------------
// Scratch
// ---------------------------------------------------------------------------
__device__ float g_q[T_SEQ * D_MODEL];
__device__ float g_k[T_SEQ * KV_DIM];
__device__ float g_v[T_SEQ * KV_DIM];
__device__ float g_y[T_SEQ * D_MODEL];
__device__ float g_scores[134217728];          // 512 MB
__device__ float g_invl[N_HEADS * T_SEQ];      // per-row 1/l

// ---------------------------------------------------------------------------
// Helpers
// ---------------------------------------------------------------------------
__device__ __forceinline__ uint32_t smem_u32(const void* p) {
    uint32_t a;
    asm("{ .reg .u64 t; cvta.to.shared.u64 t, %1; cvt.u32.u64 %0, t; }"
        : "=r"(a) : "l"(p));
    return a;
}

// pack two f32 -> f16x2, lo = first arg
__device__ __forceinline__ uint32_t pk(float lo, float hi) {
    uint32_t r;
    asm("cvt.rn.f16x2.f32 %0, %1, %2;" : "=r"(r) : "f"(hi), "f"(lo));
    return r;
}

__device__ __forceinline__ void sts16B(uint32_t addr, uint32_t w0, uint32_t w1,
                                       uint32_t w2, uint32_t w3) {
    asm volatile("st.shared.v4.b32 [%0], {%1,%2,%3,%4};"
                 :: "r"(addr), "r"(w0), "r"(w1), "r"(w2), "r"(w3) : "memory");
}

__device__ __forceinline__ void ldsm4(uint32_t& r0, uint32_t& r1, uint32_t& r2,
                                      uint32_t& r3, uint32_t a) {
    asm volatile("ldmatrix.sync.aligned.m8n8.x4.shared.b16 {%0,%1,%2,%3}, [%4];"
                 : "=r"(r0), "=r"(r1), "=r"(r2), "=r"(r3) : "r"(a));
}
__device__ __forceinline__ void ldsm4t(uint32_t& r0, uint32_t& r1, uint32_t& r2,
                                       uint32_t& r3, uint32_t a) {
    asm volatile("ldmatrix.sync.aligned.m8n8.x4.trans.shared.b16 {%0,%1,%2,%3}, [%4];"
                 : "=r"(r0), "=r"(r1), "=r"(r2), "=r"(r3) : "r"(a));
}

__device__ __forceinline__ void mma16816(float* d, uint32_t a0, uint32_t a1,
                                         uint32_t a2, uint32_t a3,
                                         uint32_t b0, uint32_t b1) {
    asm volatile(
        "mma.sync.aligned.m16n8k16.row.col.f32.f16.f16.f32 "
        "{%0,%1,%2,%3},{%4,%5,%6,%7},{%8,%9},{%0,%1,%2,%3};"
        : "+f"(d[0]), "+f"(d[1]), "+f"(d[2]), "+f"(d[3])
        : "r"(a0), "r"(a1), "r"(a2), "r"(a3), "r"(b0), "r"(b1));
}

// ---------------------------------------------------------------------------
// 64x64 warp fp16 mma over one BK=32 tile (A rows @sa, B rows @sbb, stride 80B)
// ---------------------------------------------------------------------------
__device__ __forceinline__ void mma64h(uint32_t sa, uint32_t sbb, int wm, int wn,
                                       int lane, float acc[4][8][4])
{
    const int sub = lane >> 3, rr = lane & 7;
    const uint32_t loff = ((sub & 1) * 8 + rr) * ROWB + (sub >> 1) * 16;
#pragma unroll
    for (int kk = 0; kk < 2; ++kk) {
        uint32_t a[4][4];
#pragma unroll
        for (int i = 0; i < 4; ++i)
            ldsm4(a[i][0], a[i][1], a[i][2], a[i][3],
                  sa + (wm * 64 + i * 16) * ROWB + kk * 32 + loff);
        uint32_t b[4][4];
#pragma unroll
        for (int jj = 0; jj < 4; ++jj)
            ldsm4(b[jj][0], b[jj][1], b[jj][2], b[jj][3],
                  sbb + (wn * 64 + jj * 16) * ROWB + kk * 32 + loff);
#pragma unroll
        for (int i = 0; i < 4; ++i)
#pragma unroll
            for (int jj = 0; jj < 4; ++jj) {
                mma16816(acc[i][jj * 2],     a[i][0], a[i][1], a[i][2], a[i][3],
                         b[jj][0], b[jj][2]);
                mma16816(acc[i][jj * 2 + 1], a[i][0], a[i][1], a[i][2], a[i][3],
                         b[jj][1], b[jj][3]);
            }
    }
}

__device__ __forceinline__ void store_acc64(float* __restrict__ C, int ldc,
                                            int row_base, int col_base,
                                            int wm, int wn, int lane,
                                            float acc[4][8][4], float scale)
{
    const int g = lane >> 2;
    const int t = lane & 3;
#pragma unroll
    for (int i = 0; i < 4; ++i) {
#pragma unroll
        for (int j = 0; j < 8; ++j) {
            int r = row_base + wm * 64 + i * 16 + g;
            int c = col_base + wn * 64 + j * 8 + t * 2;
            float2 v0 = make_float2(acc[i][j][0] * scale, acc[i][j][1] * scale);
            float2 v1 = make_float2(acc[i][j][2] * scale, acc[i][j][3] * scale);
            *(float2*)(C + (size_t)r * ldc + c) = v0;
            *(float2*)(C + (size_t)(r + 8) * ldc + c) = v1;
        }
    }
}

// ---------------------------------------------------------------------------
// NT staging: A 128 rows + B 256 rows, K-contig fp32 -> fp16 smem
// ---------------------------------------------------------------------------
__device__ __forceinline__ void fetch_nt(const float* __restrict__ A, int lda,
                                         const float* __restrict__ B, int ldb,
                                         int k0, float4* r, int tid)
{
    const int row0 = tid >> 2;
    const int kq = (tid & 3) * 8;
#pragma unroll
    for (int it = 0; it < 2; ++it) {
        const float* s = A + (size_t)(row0 + it * 64) * lda + k0 + kq;
        r[it * 2] = *(const float4*)s;
        r[it * 2 + 1] = *(const float4*)(s + 4);
    }
#pragma unroll
    for (int it = 0; it < 4; ++it) {
        const float* s = B + (size_t)(row0 + it * 64) * ldb + k0 + kq;
        r[4 + it * 2] = *(const float4*)s;
        r[5 + it * 2] = *(const float4*)(s + 4);
    }
}

__device__ __forceinline__ void sts_nt(uint32_t sb, const float4* r, int tid)
{
    const int row0 = tid >> 2;
    const int kb = (tid & 3) * 16;
#pragma unroll
    for (int it = 0; it < 2; ++it) {
        const float4 a = r[it * 2], b = r[it * 2 + 1];
        sts16B(sb + (row0 + it * 64) * ROWB + kb,
               pk(a.x, a.y), pk(a.z, a.w), pk(b.x, b.y), pk(b.z, b.w));
    }
#pragma unroll
    for (int it = 0; it < 4; ++it) {
        const float4 a = r[4 + it * 2], b = r[5 + it * 2];
        sts16B(sb + (128 + row0 + it * 64) * ROWB + kb,
               pk(a.x, a.y), pk(a.z, a.w), pk(b.x, b.y), pk(b.z, b.w));
    }
}

// ---------------------------------------------------------------------------
// NT core: C tile [128,256] = A[128,K] * B[256,K]^T
// Single __syncthreads per K-iter: fetch(kt+1) -> mma(kt) -> sts(kt+1) -> sync
// ---------------------------------------------------------------------------
__device__ __forceinline__ void gemm_nt_core_h(const float* Ab, const float* Bb,
                                               float* C, int K, int lda, int ldb,
                                               int ldc, int row_base, int col_base,
                                               float scale, char* sm, int tid)
{
    const uint32_t sb = smem_u32(sm);
    const int lane = tid & 31, wid = tid >> 5;
    const int wm = wid & 1, wn = wid >> 1;

    float acc[4][8][4];
#pragma unroll
    for (int i = 0; i < 4; ++i)
#pragma unroll
        for (int j = 0; j < 8; ++j)
#pragma unroll
            for (int r = 0; r < 4; ++r) acc[i][j][r] = 0.f;

    float4 r[12];
    const int NK = K / BK;

    fetch_nt(Ab, lda, Bb, ldb, 0, r, tid);
    sts_nt(sb, r, tid);
    __syncthreads();

    for (int kt = 0; kt < NK; ++kt) {
        const uint32_t s = sb + (kt & 1) * STGB;
        const bool more = (kt + 1 < NK);
        if (more) fetch_nt(Ab, lda, Bb, ldb, (kt + 1) * BK, r, tid);
        mma64h(s, s + 128 * ROWB, wm, wn, lane, acc);
        if (more) sts_nt(sb + ((kt + 1) & 1) * STGB, r, tid);
        __syncthreads();
    }
    store_acc64(C, ldc, row_base, col_base, wm, wn, lane, acc, scale);
}

__global__ __launch_bounds__(NTHREADS)
void gemm_h_nt(const float* __restrict__ A, const float* __restrict__ B,
               float* __restrict__ C, int K, int lda, int ldb, int ldc)
{
    extern __shared__ char sm[];
    gemm_nt_core_h(A + (size_t)blockIdx.y * 128 * lda,
                   B + (size_t)blockIdx.x * 256 * ldb,
                   C, K, lda, ldb, ldc,
                   blockIdx.y * 128, blockIdx.x * 256, 1.0f, sm, threadIdx.x);
}

__global__ __launch_bounds__(NTHREADS)
void gemm_h_kv(const float* __restrict__ X,
               const float* __restrict__ Wk, const float* __restrict__ Wv,
               float* __restrict__ Ko, float* __restrict__ Vo)
{
    extern __shared__ char sm[];
    const float* B = (blockIdx.z == 0) ? Wk : Wv;
    float* C = (blockIdx.z == 0) ? Ko : Vo;
    gemm_nt_core_h(X + (size_t)blockIdx.y * 128 * D_MODEL,
                   B + (size_t)blockIdx.x * 256 * D_MODEL,
                   C, D_MODEL, D_MODEL, D_MODEL, KV_DIM,
                   blockIdx.y * 128, blockIdx.x * 256, 1.0f, sm, threadIdx.x);
}

__global__ __launch_bounds__(NTHREADS)
void gemm_h_scores(const float* __restrict__ Q, const float* __restrict__ Kt,
                   float* __restrict__ S, float scale)
{
    const int h = blockIdx.z;
    const int q0 = blockIdx.y * 128;
    const int c0 = blockIdx.x * 256;
    if (c0 > q0 + 127) return;
    extern __shared__ char sm[];
    gemm_nt_core_h(Q + (size_t)q0 * D_MODEL + (size_t)h * HEAD_DIM,
                   Kt + (size_t)c0 * KV_DIM + (size_t)(h >> 2) * HEAD_DIM,
                   S + (size_t)h * T_SEQ * T_SEQ, HEAD_DIM, D_MODEL, KV_DIM, T_SEQ,
                   q0, c0, scale, sm, threadIdx.x);
}

// ---------------------------------------------------------------------------
// AV kernel: Y tile [256,128] = P[256,kmax] * V[kmax,128]
// P staged fp32->fp16 with *invl; V staged [k][n] and loaded via ldmatrix.trans.
// ---------------------------------------------------------------------------
__device__ __forceinline__ void fetch_p(const float* __restrict__ P, int k0,
                                        float4* r, int tid)
{
    const int row0 = tid >> 2;
    const int kq = (tid & 3) * 8;
#pragma unroll
    for (int it = 0; it < 4; ++it) {
        const float* s = P + (size_t)(row0 + it * 64) * T_SEQ + k0 + kq;
        r[it * 2] = *(const float4*)s;
        r[it * 2 + 1] = *(const float4*)(s + 4);
    }
}

__device__ __forceinline__ void sts_p(uint32_t sb, const float4* r,
                                      const float* inv4, int tid)
{
    const int row0 = tid >> 2;
    const int kb = (tid & 3) * 16;
#pragma unroll
    for (int it = 0; it < 4; ++it) {
        float iv = inv4[it];
        float4 a = r[it * 2], b = r[it * 2 + 1];
        sts16B(sb + (row0 + it * 64) * ROWB + kb,
               pk(a.x * iv, a.y * iv), pk(a.z * iv, a.w * iv),
               pk(b.x * iv, b.y * iv), pk(b.z * iv, b.w * iv));
    }
}

__device__ __forceinline__ void fetch_v(const float* __restrict__ V, int k0,
                                        float4* r, int tid)
{
    const int kr = tid >> 3;             // 0..31
    const int nc = (tid & 7) * 16;       // 0..112
    const float* s = V + (size_t)(k0 + kr) * KV_DIM + nc;
#pragma unroll
    for (int m = 0; m < 4; ++m) r[m] = *(const float4*)(s + m * 4);
}

__device__ __forceinline__ void sts_v(uint32_t vb, const float4* r, int tid)
{
    const int kr = tid >> 3;
    const int nc = (tid & 7) * 16;
    uint32_t addr = vb + kr * VROWB + nc * 2;
    sts16B(addr,      pk(r[0].x, r[0].y), pk(r[0].z, r[0].w),
                      pk(r[1].x, r[1].y), pk(r[1].z, r[1].w));
    sts16B(addr + 16, pk(r[2].x, r[2].y), pk(r[2].z, r[2].w),
                      pk(r[3].x, r[3].y), pk(r[3].z, r[3].w));
}

__global__ __launch_bounds__(NTHREADS)
void gemm_h_av(const float* __restrict__ Attn, const float* __restrict__ V,
               const float* __restrict__ invl, float* __restrict__ Y)
{
    extern __shared__ char sm[];
    const uint32_t sb = smem_u32(sm);
    const int h = blockIdx.z;
    const int q0 = (int)(gridDim.y - 1 - blockIdx.y) * 256;   // heavy-first
    const int tid = threadIdx.x;
    const int lane = tid & 31;
    const int wid = tid >> 5;
    const int wm = wid & 3;          // 4 x 64 = 256 rows
    const int wn = wid >> 2;         // 2 x 64 = 128 cols

    const float* Ab = Attn + (size_t)h * T_SEQ * T_SEQ + (size_t)q0 * T_SEQ;
    const float* Vb = V + (size_t)(h >> 2) * HEAD_DIM;
    float* C = Y + (size_t)h * HEAD_DIM;

    float inv4[4];
    {
        const int row0 = tid >> 2;
#pragma unroll
        for (int it = 0; it < 4; ++it)
            inv4[it] = invl[h * T_SEQ + q0 + row0 + it * 64];
    }

    const int NK = (q0 + 256) / BK;

    float acc[4][8][4];
#pragma unroll
    for (int i = 0; i < 4; ++i)
#pragma unroll
        for (int j = 0; j < 8; ++j)
#pragma unroll
            for (int r = 0; r < 4; ++r) acc[i][j][r] = 0.f;

    float4 rp[8], rv[4];

    fetch_p(Ab, 0, rp, tid);
    fetch_v(Vb, 0, rv, tid);
    sts_p(sb, rp, inv4, tid);
    sts_v(sb + 20480, rv, tid);
    __syncthreads();

    const int sub = lane >> 3, rr = lane & 7;
    const uint32_t poff = ((sub & 1) * 8 + rr) * ROWB + (sub >> 1) * 16;

    for (int kt = 0; kt < NK; ++kt) {
        const uint32_t s = sb + (kt & 1) * AV_STGB;
        const bool more = (kt + 1 < NK);
        if (more) {
            fetch_p(Ab, (kt + 1) * BK, rp, tid);
            fetch_v(Vb, (kt + 1) * BK, rv, tid);
        }
        const uint32_t vbase = s + 20480;
#pragma unroll
        for (int kk = 0; kk < 2; ++kk) {
            uint32_t a[4][4];
#pragma unroll
            for (int i = 0; i < 4; ++i)
                ldsm4(a[i][0], a[i][1], a[i][2], a[i][3],
                      s + (wm * 64 + i * 16) * ROWB + kk * 32 + poff);
            uint32_t b[4][4];
#pragma unroll
            for (int jj = 0; jj < 4; ++jj)
                ldsm4t(b[jj][0], b[jj][1], b[jj][2], b[jj][3],
                       vbase + (kk * 16 + (sub >> 1) * 8 + rr) * VROWB
                             + (wn * 64 + jj * 16) * 2 + (sub & 1) * 16);
#pragma unroll
            for (int i = 0; i < 4; ++i)
#pragma unroll
                for (int jj = 0; jj < 4; ++jj) {
                    mma16816(acc[i][jj * 2],     a[i][0], a[i][1], a[i][2], a[i][3],
                             b[jj][0], b[jj][2]);
                    mma16816(acc[i][jj * 2 + 1], a[i][0], a[i][1], a[i][2], a[i][3],
                             b[jj][1], b[jj][3]);
                }
        }
        if (more) {
            const uint32_t ns = sb + ((kt + 1) & 1) * AV_STGB;
            sts_p(ns, rp, inv4, tid);
            sts_v(ns + 20480, rv, tid);
        }
        __syncthreads();
    }

    store_acc64(C, D_MODEL, q0, 0, wm, wn, lane, acc, 1.0f);
}

// ---------------------------------------------------------------------------
// Softmax, 2 passes: (1) read -> online (m, l); (2) write exp(x-m), zero-fill.
// ---------------------------------------------------------------------------
__global__ __launch_bounds__(256)
void softmax_ml(float* __restrict__ sc, float* __restrict__ invl)
{
    const int row = blockIdx.x & (T_SEQ - 1);
    float* p = sc + (size_t)blockIdx.x * T_SEQ;
    const int len = row + 1;
    const int fill_end = (row | 255) + 1;
    const int tid = threadIdx.x;
    const int lane = tid & 31;
    const int wid = tid >> 5;
    __shared__ float rm[8], rl[8];

    float m = -3.4e38f, l = 0.f;
    for (int j = tid; j < len; j += 256) {
        float x = p[j];
        if (x > m) { l *= __expf(m - x); m = x; }
        l += __expf(x - m);
    }
#pragma unroll
    for (int o = 16; o; o >>= 1) {
        float mo = __shfl_xor_sync(0xffffffffu, m, o);
        float lo = __shfl_xor_sync(0xffffffffu, l, o);
        float M = fmaxf(m, mo);
        l = l * __expf(m - M) + lo * __expf(mo - M);
        m = M;
    }
    if (lane == 0) { rm[wid] = m; rl[wid] = l; }
    __syncthreads();
    if (wid == 0) {
        float mm = (lane < 8) ? rm[lane] : -3.4e38f;
        float ll = (lane < 8) ? rl[lane] : 0.f;
#pragma unroll
        for (int o = 4; o; o >>= 1) {
            float mo = __shfl_xor_sync(0xffffffffu, mm, o);
            float lo = __shfl_xor_sync(0xffffffffu, ll, o);
            float M = fmaxf(mm, mo);
            ll = ll * __expf(mm - M) + lo * __expf(mo - M);
            mm = M;
        }
        if (lane == 0) { rm[0] = mm; rl[0] = ll; }
    }
    __syncthreads();
    m = rm[0];
    if (tid == 0) invl[blockIdx.x] = 1.f / rl[0];

    for (int j = tid; j < len; j += 256) p[j] = __expf(p[j] - m);
    for (int j = len + tid; j < fill_end; j += 256) p[j] = 0.f;
}

// ---------------------------------------------------------------------------
// RoPE
// ---------------------------------------------------------------------------
__global__ __launch_bounds__(256)
void rope_kernel(float* __restrict__ q, float* __restrict__ k,
                 const float* __restrict__ cosp, const float* __restrict__ sinp)
{
    const int idx = blockIdx.x * blockDim.x + threadIdx.x;
    const int qpairs = T_SEQ * (D_MODEL / 2);
    const int kpairs = T_SEQ * (KV_DIM / 2);
    if (idx < qpairs) {
        int t = idx / (D_MODEL / 2);
        int p = idx % (D_MODEL / 2);
        int i = p & 63;
        float c = cosp[t * 64 + i];
        float s = sinp[t * 64 + i];
        float* ptr = q + (size_t)t * D_MODEL + p * 2;
        float x1 = ptr[0], x2 = ptr[1];
        ptr[0] = x1 * c - x2 * s;
        ptr[1] = x1 * s + x2 * c;
    } else if (idx < qpairs + kpairs) {
        int r = idx - qpairs;
        int t = r / (KV_DIM / 2);
        int p = r % (KV_DIM / 2);
        int i = p & 63;
        float c = cosp[t * 64 + i];
        float s = sinp[t * 64 + i];
        float* ptr = k + (size_t)t * KV_DIM + p * 2;
        float x1 = ptr[0], x2 = ptr[1];
        ptr[0] = x1 * c - x2 * s;
        ptr[1] = x1 * s + x2 * c;
    }
}

// ---------------------------------------------------------------------------
// Launch
// ---------------------------------------------------------------------------
extern "C" void kernel_launch(void* const* d_in, const int* in_sizes, int n_in,
                              void* d_out, int out_size)
{
    const float* x    = (const float*)d_in[0];
    const float* cosp = (const float*)d_in[1];
    const float* sinp = (const float*)d_in[2];
    const float* wq   = (const float*)d_in[3];
    const float* wk   = (const float*)d_in[4];
    const float* wv   = (const float*)d_in[5];
    const float* wo   = (const float*)d_in[6];
    float* out = (float*)d_out;

    float *q, *k, *v, *y, *sc, *il;
    cudaGetSymbolAddress((void**)&q,  g_q);
    cudaGetSymbolAddress((void**)&k,  g_k);
    cudaGetSymbolAddress((void**)&v,  g_v);
    cudaGetSymbolAddress((void**)&y,  g_y);
    cudaGetSymbolAddress((void**)&sc, g_scores);
    cudaGetSymbolAddress((void**)&il, g_invl);

    cudaFuncSetAttribute(gemm_h_nt,     cudaFuncAttributeMaxDynamicSharedMemorySize, SMEM_NT);
    cudaFuncSetAttribute(gemm_h_kv,     cudaFuncAttributeMaxDynamicSharedMemorySize, SMEM_NT);
    cudaFuncSetAttribute(gemm_h_scores, cudaFuncAttributeMaxDynamicSharedMemorySize, SMEM_NT);
    cudaFuncSetAttribute(gemm_h_av,     cudaFuncAttributeMaxDynamicSharedMemorySize, SMEM_AV);

    dim3 blk(NTHREADS);

    gemm_h_nt<<<dim3(D_MODEL / 256, T_SEQ / 128), blk, SMEM_NT>>>(
        x, wq, q, D_MODEL, D_MODEL, D_MODEL, D_MODEL);
    gemm_h_kv<<<dim3(KV_DIM / 256, T_SEQ / 128, 2), blk, SMEM_NT>>>(
        x, wk, wv, k, v);

    {
        int total = T_SEQ * (D_MODEL / 2) + T_SEQ * (KV_DIM / 2);
        rope_kernel<<<(total + 255) / 256, 256>>>(q, k, cosp, sinp);
    }

    const float scale = 0.08838834764831845f;   // 1/sqrt(128)
    gemm_h_scores<<<dim3(T_SEQ / 256, T_SEQ / 128, N_HEADS), blk, SMEM_NT>>>(q, k, sc, scale);
    softmax_ml<<<N_HEADS * T_SEQ, 256>>>(sc, il);
    gemm_h_av<<<dim3(1, T_SEQ / 256, N_HEADS), blk, SMEM_AV>>>(sc, v, il, y);

    gemm_h_nt<<<dim3(D_MODEL / 256, T_SEQ / 128), blk, SMEM_NT>>>(
        y, wo, out, D_MODEL, D_MODEL, D_MODEL, D_MODEL);
}

// round 9
// speedup vs baseline: 1.1617x; 1.1617x over previous
#include <cuda_runtime.h>
#include <cuda_fp16.h>
#include <stdint.h>
#include <math.h>

// ---------------------------------------------------------------------------
// Problem constants (B=1)
// ---------------------------------------------------------------------------
#define T_SEQ 2048
#define D_MODEL 4096
#define KV_DIM 1024
#define HEAD_DIM 128
#define N_HEADS 32

#define BK 32
#define ROWB 80                 // bytes per fp16 smem row (32 halves + pad)
#define NTHREADS 256
#define STG 30720               // (128+256) rows * 80 B
#define SMEM_NT (4 * STG)       // 122880

#define VROWB 272               // V smem row: 128 halves + pad
#define AV_STG (20480 + 8704)   // P 256*80 + V 32*272 = 29184
#define SMEM_AV (4 * AV_STG)    // 116736

// ---------------------------------------------------------------------------
// Scratch
// ---------------------------------------------------------------------------
__device__ __half g_xh[T_SEQ * D_MODEL];
__device__ __half g_wqh[D_MODEL * D_MODEL];
__device__ __half g_wkh[KV_DIM * D_MODEL];
__device__ __half g_wvh[KV_DIM * D_MODEL];
__device__ __half g_woh[D_MODEL * D_MODEL];
__device__ float  g_q[T_SEQ * D_MODEL];        // pre-rope fp32
__device__ float  g_k[T_SEQ * KV_DIM];
__device__ __half g_qh[T_SEQ * D_MODEL];
__device__ __half g_kh[T_SEQ * KV_DIM];
__device__ __half g_vh[T_SEQ * KV_DIM];
__device__ float  g_s[134217728];              // 512 MB scores fp32
__device__ __half g_p[134217728];              // 268 MB P fp16
__device__ __half g_yh[T_SEQ * D_MODEL];

// ---------------------------------------------------------------------------
// Helpers
// ---------------------------------------------------------------------------
__device__ __forceinline__ uint32_t smem_u32(const void* p) {
    uint32_t a;
    asm("{ .reg .u64 t; cvta.to.shared.u64 t, %1; cvt.u32.u64 %0, t; }"
        : "=r"(a) : "l"(p));
    return a;
}

__device__ __forceinline__ void cp16(uint32_t dst, const void* src) {
    asm volatile("cp.async.cg.shared.global [%0], [%1], 16;" :: "r"(dst), "l"(src));
}
#define CP_COMMIT() asm volatile("cp.async.commit_group;" ::: "memory")
#define CP_WAIT(n)  asm volatile("cp.async.wait_group %0;" :: "n"(n) : "memory")

__device__ __forceinline__ void ldsm4(uint32_t& r0, uint32_t& r1, uint32_t& r2,
                                      uint32_t& r3, uint32_t a) {
    asm volatile("ldmatrix.sync.aligned.m8n8.x4.shared.b16 {%0,%1,%2,%3}, [%4];"
                 : "=r"(r0), "=r"(r1), "=r"(r2), "=r"(r3) : "r"(a));
}
__device__ __forceinline__ void ldsm4t(uint32_t& r0, uint32_t& r1, uint32_t& r2,
                                       uint32_t& r3, uint32_t a) {
    asm volatile("ldmatrix.sync.aligned.m8n8.x4.trans.shared.b16 {%0,%1,%2,%3}, [%4];"
                 : "=r"(r0), "=r"(r1), "=r"(r2), "=r"(r3) : "r"(a));
}

__device__ __forceinline__ void mma16816(float* d, uint32_t a0, uint32_t a1,
                                         uint32_t a2, uint32_t a3,
                                         uint32_t b0, uint32_t b1) {
    asm volatile(
        "mma.sync.aligned.m16n8k16.row.col.f32.f16.f16.f32 "
        "{%0,%1,%2,%3},{%4,%5,%6,%7},{%8,%9},{%0,%1,%2,%3};"
        : "+f"(d[0]), "+f"(d[1]), "+f"(d[2]), "+f"(d[3])
        : "r"(a0), "r"(a1), "r"(a2), "r"(a3), "r"(b0), "r"(b1));
}

// ---------------------------------------------------------------------------
// 64x64 warp fp16 mma over one BK=32 tile (A rows @sa, B rows @sbb, 80B rows)
// ---------------------------------------------------------------------------
__device__ __forceinline__ void mma64h(uint32_t sa, uint32_t sbb, int wm, int wn,
                                       int lane, float acc[4][8][4])
{
    const int sub = lane >> 3, rr = lane & 7;
    const uint32_t loff = ((sub & 1) * 8 + rr) * ROWB + (sub >> 1) * 16;
#pragma unroll
    for (int kk = 0; kk < 2; ++kk) {
        uint32_t a[4][4];
#pragma unroll
        for (int i = 0; i < 4; ++i)
            ldsm4(a[i][0], a[i][1], a[i][2], a[i][3],
                  sa + (wm * 64 + i * 16) * ROWB + kk * 32 + loff);
        uint32_t b[4][4];
#pragma unroll
        for (int jj = 0; jj < 4; ++jj)
            ldsm4(b[jj][0], b[jj][1], b[jj][2], b[jj][3],
                  sbb + (wn * 64 + jj * 16) * ROWB + kk * 32 + loff);
#pragma unroll
        for (int i = 0; i < 4; ++i)
#pragma unroll
            for (int jj = 0; jj < 4; ++jj) {
                mma16816(acc[i][jj * 2],     a[i][0], a[i][1], a[i][2], a[i][3],
                         b[jj][0], b[jj][2]);
                mma16816(acc[i][jj * 2 + 1], a[i][0], a[i][1], a[i][2], a[i][3],
                         b[jj][1], b[jj][3]);
            }
    }
}

// Epilogue: fp32 or fp16 output
template<bool HOUT>
__device__ __forceinline__ void store_acc64(void* Cv, int ldc,
                                            int row_base, int col_base,
                                            int wm, int wn, int lane,
                                            float acc[4][8][4], float scale)
{
    const int g = lane >> 2;
    const int t = lane & 3;
#pragma unroll
    for (int i = 0; i < 4; ++i) {
#pragma unroll
        for (int j = 0; j < 8; ++j) {
            int r = row_base + wm * 64 + i * 16 + g;
            int c = col_base + wn * 64 + j * 8 + t * 2;
            if (HOUT) {
                __half* C = (__half*)Cv;
                __half2 v0 = __floats2half2_rn(acc[i][j][0] * scale, acc[i][j][1] * scale);
                __half2 v1 = __floats2half2_rn(acc[i][j][2] * scale, acc[i][j][3] * scale);
                *(__half2*)(C + (size_t)r * ldc + c) = v0;
                *(__half2*)(C + (size_t)(r + 8) * ldc + c) = v1;
            } else {
                float* C = (float*)Cv;
                float2 v0 = make_float2(acc[i][j][0] * scale, acc[i][j][1] * scale);
                float2 v1 = make_float2(acc[i][j][2] * scale, acc[i][j][3] * scale);
                *(float2*)(C + (size_t)r * ldc + c) = v0;
                *(float2*)(C + (size_t)(r + 8) * ldc + c) = v1;
            }
        }
    }
}

// ---------------------------------------------------------------------------
// cp.async staging: A 128 rows + B 256 rows of fp16, 32 halves per row
// ---------------------------------------------------------------------------
__device__ __forceinline__ void stage_nt(uint32_t dst, const __half* __restrict__ A,
                                         int lda, const __half* __restrict__ B,
                                         int ldb, int k0, int tid)
{
#pragma unroll
    for (int it = 0; it < 6; ++it) {
        int c = tid + it * NTHREADS;          // 0..1535
        int row = c >> 2;                     // 0..383
        int kh = (c & 3) * 8;                 // halves offset
        const __half* src = (row < 128)
            ? (A + (size_t)row * lda + k0 + kh)
            : (B + (size_t)(row - 128) * ldb + k0 + kh);
        cp16(dst + row * ROWB + (c & 3) * 16, src);
    }
}

// ---------------------------------------------------------------------------
// NT core: C tile [128,256] = A[128,K] * B[256,K]^T, fp16 in, 4-stage cp.async
// ---------------------------------------------------------------------------
template<bool HOUT>
__device__ __forceinline__ void gemm_core(const __half* Ab, const __half* Bb,
                                          void* C, int K, int lda, int ldb,
                                          int ldc, int row_base, int col_base,
                                          float scale, char* sm, int tid)
{
    const uint32_t sb = smem_u32(sm);
    const int lane = tid & 31, wid = tid >> 5;
    const int wm = wid & 1, wn = wid >> 1;

    float acc[4][8][4];
#pragma unroll
    for (int i = 0; i < 4; ++i)
#pragma unroll
        for (int j = 0; j < 8; ++j)
#pragma unroll
            for (int r = 0; r < 4; ++r) acc[i][j][r] = 0.f;

    const int NK = K / BK;

#pragma unroll
    for (int s = 0; s < 3; ++s) {
        stage_nt(sb + s * STG, Ab, lda, Bb, ldb, s * BK, tid);
        CP_COMMIT();
    }

    for (int kt = 0; kt < NK; ++kt) {
        CP_WAIT(2);
        __syncthreads();
        if (kt + 3 < NK)
            stage_nt(sb + ((kt + 3) & 3) * STG, Ab, lda, Bb, ldb, (kt + 3) * BK, tid);
        CP_COMMIT();
        const uint32_t s = sb + (kt & 3) * STG;
        mma64h(s, s + 128 * ROWB, wm, wn, lane, acc);
    }
    store_acc64<HOUT>(C, ldc, row_base, col_base, wm, wn, lane, acc, scale);
}

__global__ __launch_bounds__(NTHREADS)
void gemm_h_q(const __half* __restrict__ X, const __half* __restrict__ W,
              float* __restrict__ C)
{
    extern __shared__ char sm[];
    gemm_core<false>(X + (size_t)blockIdx.y * 128 * D_MODEL,
                     W + (size_t)blockIdx.x * 256 * D_MODEL,
                     C, D_MODEL, D_MODEL, D_MODEL, D_MODEL,
                     blockIdx.y * 128, blockIdx.x * 256, 1.0f, sm, threadIdx.x);
}

__global__ __launch_bounds__(NTHREADS)
void gemm_h_kv(const __half* __restrict__ X,
               const __half* __restrict__ Wk, const __half* __restrict__ Wv,
               float* __restrict__ Ko, __half* __restrict__ Vo)
{
    extern __shared__ char sm[];
    const __half* Xb = X + (size_t)blockIdx.y * 128 * D_MODEL;
    if (blockIdx.z == 0)
        gemm_core<false>(Xb, Wk + (size_t)blockIdx.x * 256 * D_MODEL,
                         Ko, D_MODEL, D_MODEL, D_MODEL, KV_DIM,
                         blockIdx.y * 128, blockIdx.x * 256, 1.0f, sm, threadIdx.x);
    else
        gemm_core<true>(Xb, Wv + (size_t)blockIdx.x * 256 * D_MODEL,
                        Vo, D_MODEL, D_MODEL, D_MODEL, KV_DIM,
                        blockIdx.y * 128, blockIdx.x * 256, 1.0f, sm, threadIdx.x);
}

__global__ __launch_bounds__(NTHREADS)
void gemm_h_o(const __half* __restrict__ Y, const __half* __restrict__ W,
              float* __restrict__ C)
{
    extern __shared__ char sm[];
    gemm_core<false>(Y + (size_t)blockIdx.y * 128 * D_MODEL,
                     W + (size_t)blockIdx.x * 256 * D_MODEL,
                     C, D_MODEL, D_MODEL, D_MODEL, D_MODEL,
                     blockIdx.y * 128, blockIdx.x * 256, 1.0f, sm, threadIdx.x);
}

__global__ __launch_bounds__(NTHREADS)
void gemm_h_scores(const __half* __restrict__ Q, const __half* __restrict__ Kt,
                   float* __restrict__ S, float scale)
{
    const int h = blockIdx.z;
    const int q0 = blockIdx.y * 128;
    const int c0 = blockIdx.x * 256;
    if (c0 > q0 + 127) return;
    extern __shared__ char sm[];
    gemm_core<false>(Q + (size_t)q0 * D_MODEL + (size_t)h * HEAD_DIM,
                     Kt + (size_t)c0 * KV_DIM + (size_t)(h >> 2) * HEAD_DIM,
                     S + (size_t)h * T_SEQ * T_SEQ, HEAD_DIM, D_MODEL, KV_DIM, T_SEQ,
                     q0, c0, scale, sm, threadIdx.x);
}

// ---------------------------------------------------------------------------
// AV: Y tile [256,128] = P[256,kmax] * V[kmax,128], fp16 in, fp16 out
// ---------------------------------------------------------------------------
__device__ __forceinline__ void stage_av(uint32_t dst, const __half* __restrict__ P,
                                         int k0, const __half* __restrict__ V, int tid)
{
#pragma unroll
    for (int it = 0; it < 4; ++it) {          // P: 256 rows x 64B
        int c = tid + it * NTHREADS;
        int row = c >> 2;
        cp16(dst + row * ROWB + (c & 3) * 16,
             P + (size_t)row * T_SEQ + k0 + (c & 3) * 8);
    }
#pragma unroll
    for (int it = 0; it < 2; ++it) {          // V: 32 rows x 256B
        int c = tid + it * NTHREADS;
        int kr = c >> 4;
        cp16(dst + 20480 + kr * VROWB + (c & 15) * 16,
             V + (size_t)(k0 + kr) * KV_DIM + (c & 15) * 8);
    }
}

__global__ __launch_bounds__(NTHREADS)
void gemm_h_av(const __half* __restrict__ Pm, const __half* __restrict__ V,
               __half* __restrict__ Y)
{
    extern __shared__ char sm[];
    const uint32_t sb = smem_u32(sm);
    const int h = blockIdx.z;
    const int q0 = (int)(gridDim.y - 1 - blockIdx.y) * 256;   // heavy-first
    const int tid = threadIdx.x;
    const int lane = tid & 31;
    const int wid = tid >> 5;
    const int wm = wid & 3;          // 4 x 64 = 256 rows
    const int wn = wid >> 2;         // 2 x 64 = 128 cols

    const __half* Ab = Pm + (size_t)h * T_SEQ * T_SEQ + (size_t)q0 * T_SEQ;
    const __half* Vb = V + (size_t)(h >> 2) * HEAD_DIM;
    __half* C = Y + (size_t)h * HEAD_DIM;

    const int NK = (q0 + 256) / BK;

    float acc[4][8][4];
#pragma unroll
    for (int i = 0; i < 4; ++i)
#pragma unroll
        for (int j = 0; j < 8; ++j)
#pragma unroll
            for (int r = 0; r < 4; ++r) acc[i][j][r] = 0.f;

#pragma unroll
    for (int s = 0; s < 3; ++s) {
        stage_av(sb + s * AV_STG, Ab, s * BK, Vb, tid);
        CP_COMMIT();
    }

    const int sub = lane >> 3, rr = lane & 7;
    const uint32_t poff = ((sub & 1) * 8 + rr) * ROWB + (sub >> 1) * 16;

    for (int kt = 0; kt < NK; ++kt) {
        CP_WAIT(2);
        __syncthreads();
        if (kt + 3 < NK)
            stage_av(sb + ((kt + 3) & 3) * AV_STG, Ab, (kt + 3) * BK, Vb, tid);
        CP_COMMIT();
        const uint32_t s = sb + (kt & 3) * AV_STG;
        const uint32_t vbase = s + 20480;
#pragma unroll
        for (int kk = 0; kk < 2; ++kk) {
            uint32_t a[4][4];
#pragma unroll
            for (int i = 0; i < 4; ++i)
                ldsm4(a[i][0], a[i][1], a[i][2], a[i][3],
                      s + (wm * 64 + i * 16) * ROWB + kk * 32 + poff);
            uint32_t b[4][4];
#pragma unroll
            for (int jj = 0; jj < 4; ++jj)
                ldsm4t(b[jj][0], b[jj][1], b[jj][2], b[jj][3],
                       vbase + (kk * 16 + (sub >> 1) * 8 + rr) * VROWB
                             + (wn * 64 + jj * 16) * 2 + (sub & 1) * 16);
#pragma unroll
            for (int i = 0; i < 4; ++i)
#pragma unroll
                for (int jj = 0; jj < 4; ++jj) {
                    mma16816(acc[i][jj * 2],     a[i][0], a[i][1], a[i][2], a[i][3],
                             b[jj][0], b[jj][2]);
                    mma16816(acc[i][jj * 2 + 1], a[i][0], a[i][1], a[i][2], a[i][3],
                             b[jj][1], b[jj][3]);
                }
        }
    }

    store_acc64<true>(C, D_MODEL, q0, 0, wm, wn, lane, acc, 1.0f);
}

// ---------------------------------------------------------------------------
// Softmax: single fp32 read (row in registers) -> fp16 P with invl folded.
// ---------------------------------------------------------------------------
__global__ __launch_bounds__(256)
void softmax_p(const float* __restrict__ sc, __half* __restrict__ pd)
{
    const int row = blockIdx.x & (T_SEQ - 1);
    const float* p = sc + (size_t)blockIdx.x * T_SEQ;
    __half* o = pd + (size_t)blockIdx.x * T_SEQ;
    const int len = row + 1;
    const int fill_end = (row | 255) + 1;
    const int tid = threadIdx.x;
    const int lane = tid & 31;
    const int wid = tid >> 5;
    __shared__ float rm[8], rl[8];

    float r[8];
    float m = -3.4e38f, l = 0.f;
#pragma unroll
    for (int it = 0; it < 8; ++it) {
        int j = tid + it * 256;
        if (j < len) {
            float x = p[j];
            r[it] = x;
            if (x > m) { l *= __expf(m - x); m = x; }
            l += __expf(x - m);
        }
    }
#pragma unroll
    for (int off = 16; off; off >>= 1) {
        float mo = __shfl_xor_sync(0xffffffffu, m, off);
        float lo = __shfl_xor_sync(0xffffffffu, l, off);
        float M = fmaxf(m, mo);
        l = l * __expf(m - M) + lo * __expf(mo - M);
        m = M;
    }
    if (lane == 0) { rm[wid] = m; rl[wid] = l; }
    __syncthreads();
    if (wid == 0) {
        float mm = (lane < 8) ? rm[lane] : -3.4e38f;
        float ll = (lane < 8) ? rl[lane] : 0.f;
#pragma unroll
        for (int off = 4; off; off >>= 1) {
            float mo = __shfl_xor_sync(0xffffffffu, mm, off);
            float lo = __shfl_xor_sync(0xffffffffu, ll, off);
            float M = fmaxf(mm, mo);
            ll = ll * __expf(mm - M) + lo * __expf(mo - M);
            mm = M;
        }
        if (lane == 0) { rm[0] = mm; rl[0] = ll; }
    }
    __syncthreads();
    m = rm[0];
    const float invl = 1.f / rl[0];

#pragma unroll
    for (int it = 0; it < 8; ++it) {
        int j = tid + it * 256;
        if (j < len)
            o[j] = __float2half_rn(__expf(r[it] - m) * invl);
        else if (j < fill_end)
            o[j] = __float2half_rn(0.f);
    }
}

// ---------------------------------------------------------------------------
// RoPE: fp32 q,k -> rotate -> fp16 qh,kh
// ---------------------------------------------------------------------------
__global__ __launch_bounds__(256)
void rope_h(const float* __restrict__ q, const float* __restrict__ k,
            __half* __restrict__ qh, __half* __restrict__ kh,
            const float* __restrict__ cosp, const float* __restrict__ sinp)
{
    const int idx = blockIdx.x * blockDim.x + threadIdx.x;
    const int qpairs = T_SEQ * (D_MODEL / 2);
    const int kpairs = T_SEQ * (KV_DIM / 2);
    if (idx < qpairs) {
        int t = idx / (D_MODEL / 2);
        int p = idx % (D_MODEL / 2);
        int i = p & 63;
        float c = cosp[t * 64 + i];
        float s = sinp[t * 64 + i];
        const float* ptr = q + (size_t)t * D_MODEL + p * 2;
        float x1 = ptr[0], x2 = ptr[1];
        *(__half2*)(qh + (size_t)t * D_MODEL + p * 2) =
            __floats2half2_rn(x1 * c - x2 * s, x1 * s + x2 * c);
    } else if (idx < qpairs + kpairs) {
        int rI = idx - qpairs;
        int t = rI / (KV_DIM / 2);
        int p = rI % (KV_DIM / 2);
        int i = p & 63;
        float c = cosp[t * 64 + i];
        float s = sinp[t * 64 + i];
        const float* ptr = k + (size_t)t * KV_DIM + p * 2;
        float x1 = ptr[0], x2 = ptr[1];
        *(__half2*)(kh + (size_t)t * KV_DIM + p * 2) =
            __floats2half2_rn(x1 * c - x2 * s, x1 * s + x2 * c);
    }
}

// ---------------------------------------------------------------------------
// fp32 -> fp16 convert (vectorized)
// ---------------------------------------------------------------------------
__global__ __launch_bounds__(256)
void cvt16(const float* __restrict__ in, __half* __restrict__ out, int n4)
{
    int i = blockIdx.x * 256 + threadIdx.x;
    if (i < n4) {
        float4 v = ((const float4*)in)[i];
        __half2 h0 = __floats2half2_rn(v.x, v.y);
        __half2 h1 = __floats2half2_rn(v.z, v.w);
        ((__half2*)out)[i * 2] = h0;
        ((__half2*)out)[i * 2 + 1] = h1;
    }
}

// ---------------------------------------------------------------------------
// Launch
// ---------------------------------------------------------------------------
extern "C" void kernel_launch(void* const* d_in, const int* in_sizes, int n_in,
                              void* d_out, int out_size)
{
    const float* x    = (const float*)d_in[0];
    const float* cosp = (const float*)d_in[1];
    const float* sinp = (const float*)d_in[2];
    const float* wq   = (const float*)d_in[3];
    const float* wk   = (const float*)d_in[4];
    const float* wv   = (const float*)d_in[5];
    const float* wo   = (const float*)d_in[6];
    float* out = (float*)d_out;

    __half *xh, *wqh, *wkh, *wvh, *woh, *qh, *kh, *vh, *ph, *yh;
    float *q, *k, *s;
    cudaGetSymbolAddress((void**)&xh,  g_xh);
    cudaGetSymbolAddress((void**)&wqh, g_wqh);
    cudaGetSymbolAddress((void**)&wkh, g_wkh);
    cudaGetSymbolAddress((void**)&wvh, g_wvh);
    cudaGetSymbolAddress((void**)&woh, g_woh);
    cudaGetSymbolAddress((void**)&q,   g_q);
    cudaGetSymbolAddress((void**)&k,   g_k);
    cudaGetSymbolAddress((void**)&qh,  g_qh);
    cudaGetSymbolAddress((void**)&kh,  g_kh);
    cudaGetSymbolAddress((void**)&vh,  g_vh);
    cudaGetSymbolAddress((void**)&s,   g_s);
    cudaGetSymbolAddress((void**)&ph,  g_p);
    cudaGetSymbolAddress((void**)&yh,  g_yh);

    cudaFuncSetAttribute(gemm_h_q,      cudaFuncAttributeMaxDynamicSharedMemorySize, SMEM_NT);
    cudaFuncSetAttribute(gemm_h_kv,     cudaFuncAttributeMaxDynamicSharedMemorySize, SMEM_NT);
    cudaFuncSetAttribute(gemm_h_o,      cudaFuncAttributeMaxDynamicSharedMemorySize, SMEM_NT);
    cudaFuncSetAttribute(gemm_h_scores, cudaFuncAttributeMaxDynamicSharedMemorySize, SMEM_NT);
    cudaFuncSetAttribute(gemm_h_av,     cudaFuncAttributeMaxDynamicSharedMemorySize, SMEM_AV);

    dim3 blk(NTHREADS);

    // fp32 -> fp16 pre-converts
    {
        int n;
        n = T_SEQ * D_MODEL / 4;   cvt16<<<(n + 255) / 256, 256>>>(x,  xh,  n);
        n = D_MODEL * D_MODEL / 4; cvt16<<<(n + 255) / 256, 256>>>(wq, wqh, n);
        n = KV_DIM * D_MODEL / 4;  cvt16<<<(n + 255) / 256, 256>>>(wk, wkh, n);
        n = KV_DIM * D_MODEL / 4;  cvt16<<<(n + 255) / 256, 256>>>(wv, wvh, n);
        n = D_MODEL * D_MODEL / 4; cvt16<<<(n + 255) / 256, 256>>>(wo, woh, n);
    }

    gemm_h_q<<<dim3(D_MODEL / 256, T_SEQ / 128), blk, SMEM_NT>>>(xh, wqh, q);
    gemm_h_kv<<<dim3(KV_DIM / 256, T_SEQ / 128, 2), blk, SMEM_NT>>>(xh, wkh, wvh, k, vh);

    {
        int total = T_SEQ * (D_MODEL / 2) + T_SEQ * (KV_DIM / 2);
        rope_h<<<(total + 255) / 256, 256>>>(q, k, qh, kh, cosp, sinp);
    }

    const float scale = 0.08838834764831845f;   // 1/sqrt(128)
    gemm_h_scores<<<dim3(T_SEQ / 256, T_SEQ / 128, N_HEADS), blk, SMEM_NT>>>(qh, kh, s, scale);
    softmax_p<<<N_HEADS * T_SEQ, 256>>>(s, ph);
    gemm_h_av<<<dim3(1, T_SEQ / 256, N_HEADS), blk, SMEM_AV>>>(ph, vh, yh);

    gemm_h_o<<<dim3(D_MODEL / 256, T_SEQ / 128), blk, SMEM_NT>>>(yh, woh, out);
}

// round 10
// speedup vs baseline: 1.2240x; 1.0536x over previous
#include <cuda_runtime.h>
#include <cuda_fp16.h>
#include <stdint.h>
#include <math.h>

// ---------------------------------------------------------------------------
// Problem constants (B=1)
// ---------------------------------------------------------------------------
#define T_SEQ 2048
#define D_MODEL 4096
#define KV_DIM 1024
#define HEAD_DIM 128
#define N_HEADS 32

#define BK 32
#define ROWB 80                 // bytes per fp16 smem row (32 halves + pad)
#define GTHREADS 512            // GEMM kernels: 16 warps
#define STG 30720               // (128+256) rows * 80 B
#define SMEM_NT (4 * STG)       // 122880

#define VROWB 272               // V smem row: 128 halves + pad
#define AV_STG (20480 + 8704)   // P 256*80 + V 32*272 = 29184
#define SMEM_AV (4 * AV_STG)    // 116736

// ---------------------------------------------------------------------------
// Scratch
// ---------------------------------------------------------------------------
__device__ __half g_xh[T_SEQ * D_MODEL];
__device__ __half g_wqh[D_MODEL * D_MODEL];
__device__ __half g_wkh[KV_DIM * D_MODEL];
__device__ __half g_wvh[KV_DIM * D_MODEL];
__device__ __half g_woh[D_MODEL * D_MODEL];
__device__ float  g_q[T_SEQ * D_MODEL];        // pre-rope fp32
__device__ float  g_k[T_SEQ * KV_DIM];
__device__ __half g_qh[T_SEQ * D_MODEL];
__device__ __half g_kh[T_SEQ * KV_DIM];
__device__ __half g_vh[T_SEQ * KV_DIM];
__device__ float  g_s[134217728];              // 512 MB scores fp32
__device__ __half g_p[134217728];              // 268 MB P fp16
__device__ __half g_yh[T_SEQ * D_MODEL];

// ---------------------------------------------------------------------------
// Helpers
// ---------------------------------------------------------------------------
__device__ __forceinline__ uint32_t smem_u32(const void* p) {
    uint32_t a;
    asm("{ .reg .u64 t; cvta.to.shared.u64 t, %1; cvt.u32.u64 %0, t; }"
        : "=r"(a) : "l"(p));
    return a;
}

__device__ __forceinline__ void cp16(uint32_t dst, const void* src) {
    asm volatile("cp.async.cg.shared.global [%0], [%1], 16;" :: "r"(dst), "l"(src));
}
#define CP_COMMIT() asm volatile("cp.async.commit_group;" ::: "memory")
#define CP_WAIT(n)  asm volatile("cp.async.wait_group %0;" :: "n"(n) : "memory")

__device__ __forceinline__ void ldsm4(uint32_t& r0, uint32_t& r1, uint32_t& r2,
                                      uint32_t& r3, uint32_t a) {
    asm volatile("ldmatrix.sync.aligned.m8n8.x4.shared.b16 {%0,%1,%2,%3}, [%4];"
                 : "=r"(r0), "=r"(r1), "=r"(r2), "=r"(r3) : "r"(a));
}
__device__ __forceinline__ void ldsm4t(uint32_t& r0, uint32_t& r1, uint32_t& r2,
                                       uint32_t& r3, uint32_t a) {
    asm volatile("ldmatrix.sync.aligned.m8n8.x4.trans.shared.b16 {%0,%1,%2,%3}, [%4];"
                 : "=r"(r0), "=r"(r1), "=r"(r2), "=r"(r3) : "r"(a));
}

__device__ __forceinline__ void mma16816(float* d, uint32_t a0, uint32_t a1,
                                         uint32_t a2, uint32_t a3,
                                         uint32_t b0, uint32_t b1) {
    asm volatile(
        "mma.sync.aligned.m16n8k16.row.col.f32.f16.f16.f32 "
        "{%0,%1,%2,%3},{%4,%5,%6,%7},{%8,%9},{%0,%1,%2,%3};"
        : "+f"(d[0]), "+f"(d[1]), "+f"(d[2]), "+f"(d[3])
        : "r"(a0), "r"(a1), "r"(a2), "r"(a3), "r"(b0), "r"(b1));
}

// ---------------------------------------------------------------------------
// 32x64 warp fp16 mma over one BK=32 tile. acc[2][8][4].
// A rows at sa + (wm*32..), B rows at sbb + (wn*64..); 80-byte rows.
// ---------------------------------------------------------------------------
__device__ __forceinline__ void mma32x64(uint32_t sa, uint32_t sbb, int wm, int wn,
                                         int lane, float acc[2][8][4])
{
    const int sub = lane >> 3, rr = lane & 7;
    const uint32_t loff = ((sub & 1) * 8 + rr) * ROWB + (sub >> 1) * 16;
#pragma unroll
    for (int kk = 0; kk < 2; ++kk) {
        uint32_t a[2][4];
#pragma unroll
        for (int i = 0; i < 2; ++i)
            ldsm4(a[i][0], a[i][1], a[i][2], a[i][3],
                  sa + (wm * 32 + i * 16) * ROWB + kk * 32 + loff);
        uint32_t b[4][4];
#pragma unroll
        for (int jj = 0; jj < 4; ++jj)
            ldsm4(b[jj][0], b[jj][1], b[jj][2], b[jj][3],
                  sbb + (wn * 64 + jj * 16) * ROWB + kk * 32 + loff);
#pragma unroll
        for (int i = 0; i < 2; ++i)
#pragma unroll
            for (int jj = 0; jj < 4; ++jj) {
                mma16816(acc[i][jj * 2],     a[i][0], a[i][1], a[i][2], a[i][3],
                         b[jj][0], b[jj][2]);
                mma16816(acc[i][jj * 2 + 1], a[i][0], a[i][1], a[i][2], a[i][3],
                         b[jj][1], b[jj][3]);
            }
    }
}

// Epilogue (32 rows x 64 cols per warp): fp32 or fp16 output
template<bool HOUT>
__device__ __forceinline__ void store_acc32(void* Cv, int ldc,
                                            int row_base, int col_base,
                                            int wm, int wn, int lane,
                                            float acc[2][8][4], float scale)
{
    const int g = lane >> 2;
    const int t = lane & 3;
#pragma unroll
    for (int i = 0; i < 2; ++i) {
#pragma unroll
        for (int j = 0; j < 8; ++j) {
            int r = row_base + wm * 32 + i * 16 + g;
            int c = col_base + wn * 64 + j * 8 + t * 2;
            if (HOUT) {
                __half* C = (__half*)Cv;
                *(__half2*)(C + (size_t)r * ldc + c) =
                    __floats2half2_rn(acc[i][j][0] * scale, acc[i][j][1] * scale);
                *(__half2*)(C + (size_t)(r + 8) * ldc + c) =
                    __floats2half2_rn(acc[i][j][2] * scale, acc[i][j][3] * scale);
            } else {
                float* C = (float*)Cv;
                *(float2*)(C + (size_t)r * ldc + c) =
                    make_float2(acc[i][j][0] * scale, acc[i][j][1] * scale);
                *(float2*)(C + (size_t)(r + 8) * ldc + c) =
                    make_float2(acc[i][j][2] * scale, acc[i][j][3] * scale);
            }
        }
    }
}

// ---------------------------------------------------------------------------
// cp.async staging: A 128 rows + B 256 rows of fp16, 32 halves per row
// 1536 16B-chunks over 512 threads = 3 iterations
// ---------------------------------------------------------------------------
__device__ __forceinline__ void stage_nt(uint32_t dst, const __half* __restrict__ A,
                                         int lda, const __half* __restrict__ B,
                                         int ldb, int k0, int tid)
{
#pragma unroll
    for (int it = 0; it < 3; ++it) {
        int c = tid + it * GTHREADS;          // 0..1535
        int row = c >> 2;                     // 0..383
        int kh = (c & 3) * 8;
        const __half* src = (row < 128)
            ? (A + (size_t)row * lda + k0 + kh)
            : (B + (size_t)(row - 128) * ldb + k0 + kh);
        cp16(dst + row * ROWB + (c & 3) * 16, src);
    }
}

// ---------------------------------------------------------------------------
// NT core: C tile [128,256] = A[128,K] * B[256,K]^T, fp16 in, 4-stage cp.async
// 16 warps: wm = wid&3 (4x32 rows), wn = wid>>2 (4x64 cols)
// ---------------------------------------------------------------------------
template<bool HOUT>
__device__ __forceinline__ void gemm_core(const __half* Ab, const __half* Bb,
                                          void* C, int K, int lda, int ldb,
                                          int ldc, int row_base, int col_base,
                                          float scale, char* sm, int tid)
{
    const uint32_t sb = smem_u32(sm);
    const int lane = tid & 31, wid = tid >> 5;
    const int wm = wid & 3, wn = wid >> 2;

    float acc[2][8][4];
#pragma unroll
    for (int i = 0; i < 2; ++i)
#pragma unroll
        for (int j = 0; j < 8; ++j)
#pragma unroll
            for (int r = 0; r < 4; ++r) acc[i][j][r] = 0.f;

    const int NK = K / BK;

#pragma unroll
    for (int s = 0; s < 3; ++s) {
        stage_nt(sb + s * STG, Ab, lda, Bb, ldb, s * BK, tid);
        CP_COMMIT();
    }

    for (int kt = 0; kt < NK; ++kt) {
        CP_WAIT(2);
        __syncthreads();
        if (kt + 3 < NK)
            stage_nt(sb + ((kt + 3) & 3) * STG, Ab, lda, Bb, ldb, (kt + 3) * BK, tid);
        CP_COMMIT();
        const uint32_t s = sb + (kt & 3) * STG;
        mma32x64(s, s + 128 * ROWB, wm, wn, lane, acc);
    }
    store_acc32<HOUT>(C, ldc, row_base, col_base, wm, wn, lane, acc, scale);
}

__global__ __launch_bounds__(GTHREADS)
void gemm_h_q(const __half* __restrict__ X, const __half* __restrict__ W,
              float* __restrict__ C)
{
    extern __shared__ char sm[];
    gemm_core<false>(X + (size_t)blockIdx.y * 128 * D_MODEL,
                     W + (size_t)blockIdx.x * 256 * D_MODEL,
                     C, D_MODEL, D_MODEL, D_MODEL, D_MODEL,
                     blockIdx.y * 128, blockIdx.x * 256, 1.0f, sm, threadIdx.x);
}

__global__ __launch_bounds__(GTHREADS)
void gemm_h_kv(const __half* __restrict__ X,
               const __half* __restrict__ Wk, const __half* __restrict__ Wv,
               float* __restrict__ Ko, __half* __restrict__ Vo)
{
    extern __shared__ char sm[];
    const __half* Xb = X + (size_t)blockIdx.y * 128 * D_MODEL;
    if (blockIdx.z == 0)
        gemm_core<false>(Xb, Wk + (size_t)blockIdx.x * 256 * D_MODEL,
                         Ko, D_MODEL, D_MODEL, D_MODEL, KV_DIM,
                         blockIdx.y * 128, blockIdx.x * 256, 1.0f, sm, threadIdx.x);
    else
        gemm_core<true>(Xb, Wv + (size_t)blockIdx.x * 256 * D_MODEL,
                        Vo, D_MODEL, D_MODEL, D_MODEL, KV_DIM,
                        blockIdx.y * 128, blockIdx.x * 256, 1.0f, sm, threadIdx.x);
}

__global__ __launch_bounds__(GTHREADS)
void gemm_h_o(const __half* __restrict__ Y, const __half* __restrict__ W,
              float* __restrict__ C)
{
    extern __shared__ char sm[];
    gemm_core<false>(Y + (size_t)blockIdx.y * 128 * D_MODEL,
                     W + (size_t)blockIdx.x * 256 * D_MODEL,
                     C, D_MODEL, D_MODEL, D_MODEL, D_MODEL,
                     blockIdx.y * 128, blockIdx.x * 256, 1.0f, sm, threadIdx.x);
}

__global__ __launch_bounds__(GTHREADS)
void gemm_h_scores(const __half* __restrict__ Q, const __half* __restrict__ Kt,
                   float* __restrict__ S, float scale)
{
    const int h = blockIdx.z;
    const int q0 = blockIdx.y * 128;
    const int c0 = blockIdx.x * 256;
    if (c0 > q0 + 127) return;
    extern __shared__ char sm[];
    gemm_core<false>(Q + (size_t)q0 * D_MODEL + (size_t)h * HEAD_DIM,
                     Kt + (size_t)c0 * KV_DIM + (size_t)(h >> 2) * HEAD_DIM,
                     S + (size_t)h * T_SEQ * T_SEQ, HEAD_DIM, D_MODEL, KV_DIM, T_SEQ,
                     q0, c0, scale, sm, threadIdx.x);
}

// ---------------------------------------------------------------------------
// AV: Y tile [256,128] = P[256,kmax] * V[kmax,128]
// 16 warps: wm = wid&7 (8x32 rows), wn = wid>>3 (2x64 cols)
// ---------------------------------------------------------------------------
__device__ __forceinline__ void stage_av(uint32_t dst, const __half* __restrict__ P,
                                         int k0, const __half* __restrict__ V, int tid)
{
#pragma unroll
    for (int it = 0; it < 2; ++it) {          // P: 256 rows x 64B = 1024 chunks
        int c = tid + it * GTHREADS;
        int row = c >> 2;
        cp16(dst + row * ROWB + (c & 3) * 16,
             P + (size_t)row * T_SEQ + k0 + (c & 3) * 8);
    }
    {                                          // V: 32 rows x 256B = 512 chunks
        int c = tid;
        int kr = c >> 4;
        cp16(dst + 20480 + kr * VROWB + (c & 15) * 16,
             V + (size_t)(k0 + kr) * KV_DIM + (c & 15) * 8);
    }
}

__global__ __launch_bounds__(GTHREADS)
void gemm_h_av(const __half* __restrict__ Pm, const __half* __restrict__ V,
               __half* __restrict__ Y)
{
    extern __shared__ char sm[];
    const uint32_t sb = smem_u32(sm);
    const int h = blockIdx.z;
    const int q0 = (int)(gridDim.y - 1 - blockIdx.y) * 256;   // heavy-first
    const int tid = threadIdx.x;
    const int lane = tid & 31;
    const int wid = tid >> 5;
    const int wm = wid & 7;          // 8 x 32 = 256 rows
    const int wn = wid >> 3;         // 2 x 64 = 128 cols

    const __half* Ab = Pm + (size_t)h * T_SEQ * T_SEQ + (size_t)q0 * T_SEQ;
    const __half* Vb = V + (size_t)(h >> 2) * HEAD_DIM;
    __half* C = Y + (size_t)h * HEAD_DIM;

    const int NK = (q0 + 256) / BK;

    float acc[2][8][4];
#pragma unroll
    for (int i = 0; i < 2; ++i)
#pragma unroll
        for (int j = 0; j < 8; ++j)
#pragma unroll
            for (int r = 0; r < 4; ++r) acc[i][j][r] = 0.f;

#pragma unroll
    for (int s = 0; s < 3; ++s) {
        stage_av(sb + s * AV_STG, Ab, s * BK, Vb, tid);
        CP_COMMIT();
    }

    const int sub = lane >> 3, rr = lane & 7;
    const uint32_t poff = ((sub & 1) * 8 + rr) * ROWB + (sub >> 1) * 16;

    for (int kt = 0; kt < NK; ++kt) {
        CP_WAIT(2);
        __syncthreads();
        if (kt + 3 < NK)
            stage_av(sb + ((kt + 3) & 3) * AV_STG, Ab, (kt + 3) * BK, Vb, tid);
        CP_COMMIT();
        const uint32_t s = sb + (kt & 3) * AV_STG;
        const uint32_t vbase = s + 20480;
#pragma unroll
        for (int kk = 0; kk < 2; ++kk) {
            uint32_t a[2][4];
#pragma unroll
            for (int i = 0; i < 2; ++i)
                ldsm4(a[i][0], a[i][1], a[i][2], a[i][3],
                      s + (wm * 32 + i * 16) * ROWB + kk * 32 + poff);
            uint32_t b[4][4];
#pragma unroll
            for (int jj = 0; jj < 4; ++jj)
                ldsm4t(b[jj][0], b[jj][1], b[jj][2], b[jj][3],
                       vbase + (kk * 16 + (sub >> 1) * 8 + rr) * VROWB
                             + (wn * 64 + jj * 16) * 2 + (sub & 1) * 16);
#pragma unroll
            for (int i = 0; i < 2; ++i)
#pragma unroll
                for (int jj = 0; jj < 4; ++jj) {
                    mma16816(acc[i][jj * 2],     a[i][0], a[i][1], a[i][2], a[i][3],
                             b[jj][0], b[jj][2]);
                    mma16816(acc[i][jj * 2 + 1], a[i][0], a[i][1], a[i][2], a[i][3],
                             b[jj][1], b[jj][3]);
                }
        }
    }

    store_acc32<true>(C, D_MODEL, q0, 0, wm, wn, lane, acc, 1.0f);
}

// ---------------------------------------------------------------------------
// Softmax: single fp32 read (row in registers) -> fp16 P with invl folded.
// ---------------------------------------------------------------------------
__global__ __launch_bounds__(256)
void softmax_p(const float* __restrict__ sc, __half* __restrict__ pd)
{
    const int row = blockIdx.x & (T_SEQ - 1);
    const float* p = sc + (size_t)blockIdx.x * T_SEQ;
    __half* o = pd + (size_t)blockIdx.x * T_SEQ;
    const int len = row + 1;
    const int fill_end = (row | 255) + 1;
    const int tid = threadIdx.x;
    const int lane = tid & 31;
    const int wid = tid >> 5;
    __shared__ float rm[8], rl[8];

    float r[8];
    float m = -3.4e38f, l = 0.f;
#pragma unroll
    for (int it = 0; it < 8; ++it) {
        int j = tid + it * 256;
        if (j < len) {
            float x = p[j];
            r[it] = x;
            if (x > m) { l *= __expf(m - x); m = x; }
            l += __expf(x - m);
        }
    }
#pragma unroll
    for (int off = 16; off; off >>= 1) {
        float mo = __shfl_xor_sync(0xffffffffu, m, off);
        float lo = __shfl_xor_sync(0xffffffffu, l, off);
        float M = fmaxf(m, mo);
        l = l * __expf(m - M) + lo * __expf(mo - M);
        m = M;
    }
    if (lane == 0) { rm[wid] = m; rl[wid] = l; }
    __syncthreads();
    if (wid == 0) {
        float mm = (lane < 8) ? rm[lane] : -3.4e38f;
        float ll = (lane < 8) ? rl[lane] : 0.f;
#pragma unroll
        for (int off = 4; off; off >>= 1) {
            float mo = __shfl_xor_sync(0xffffffffu, mm, off);
            float lo = __shfl_xor_sync(0xffffffffu, ll, off);
            float M = fmaxf(mm, mo);
            ll = ll * __expf(mm - M) + lo * __expf(mo - M);
            mm = M;
        }
        if (lane == 0) { rm[0] = mm; rl[0] = ll; }
    }
    __syncthreads();
    m = rm[0];
    const float invl = 1.f / rl[0];

#pragma unroll
    for (int it = 0; it < 8; ++it) {
        int j = tid + it * 256;
        if (j < len)
            o[j] = __float2half_rn(__expf(r[it] - m) * invl);
        else if (j < fill_end)
            o[j] = __float2half_rn(0.f);
    }
}

// ---------------------------------------------------------------------------
// RoPE: fp32 q,k -> rotate -> fp16 qh,kh
// ---------------------------------------------------------------------------
__global__ __launch_bounds__(256)
void rope_h(const float* __restrict__ q, const float* __restrict__ k,
            __half* __restrict__ qh, __half* __restrict__ kh,
            const float* __restrict__ cosp, const float* __restrict__ sinp)
{
    const int idx = blockIdx.x * blockDim.x + threadIdx.x;
    const int qpairs = T_SEQ * (D_MODEL / 2);
    const int kpairs = T_SEQ * (KV_DIM / 2);
    if (idx < qpairs) {
        int t = idx / (D_MODEL / 2);
        int p = idx % (D_MODEL / 2);
        int i = p & 63;
        float c = cosp[t * 64 + i];
        float s = sinp[t * 64 + i];
        const float* ptr = q + (size_t)t * D_MODEL + p * 2;
        float x1 = ptr[0], x2 = ptr[1];
        *(__half2*)(qh + (size_t)t * D_MODEL + p * 2) =
            __floats2half2_rn(x1 * c - x2 * s, x1 * s + x2 * c);
    } else if (idx < qpairs + kpairs) {
        int rI = idx - qpairs;
        int t = rI / (KV_DIM / 2);
        int p = rI % (KV_DIM / 2);
        int i = p & 63;
        float c = cosp[t * 64 + i];
        float s = sinp[t * 64 + i];
        const float* ptr = k + (size_t)t * KV_DIM + p * 2;
        float x1 = ptr[0], x2 = ptr[1];
        *(__half2*)(kh + (size_t)t * KV_DIM + p * 2) =
            __floats2half2_rn(x1 * c - x2 * s, x1 * s + x2 * c);
    }
}

// ---------------------------------------------------------------------------
// fp32 -> fp16 convert (vectorized)
// ---------------------------------------------------------------------------
__global__ __launch_bounds__(256)
void cvt16(const float* __restrict__ in, __half* __restrict__ out, int n4)
{
    int i = blockIdx.x * 256 + threadIdx.x;
    if (i < n4) {
        float4 v = ((const float4*)in)[i];
        ((__half2*)out)[i * 2]     = __floats2half2_rn(v.x, v.y);
        ((__half2*)out)[i * 2 + 1] = __floats2half2_rn(v.z, v.w);
    }
}

// ---------------------------------------------------------------------------
// Launch
// ---------------------------------------------------------------------------
extern "C" void kernel_launch(void* const* d_in, const int* in_sizes, int n_in,
                              void* d_out, int out_size)
{
    const float* x    = (const float*)d_in[0];
    const float* cosp = (const float*)d_in[1];
    const float* sinp = (const float*)d_in[2];
    const float* wq   = (const float*)d_in[3];
    const float* wk   = (const float*)d_in[4];
    const float* wv   = (const float*)d_in[5];
    const float* wo   = (const float*)d_in[6];
    float* out = (float*)d_out;

    __half *xh, *wqh, *wkh, *wvh, *woh, *qh, *kh, *vh, *ph, *yh;
    float *q, *k, *s;
    cudaGetSymbolAddress((void**)&xh,  g_xh);
    cudaGetSymbolAddress((void**)&wqh, g_wqh);
    cudaGetSymbolAddress((void**)&wkh, g_wkh);
    cudaGetSymbolAddress((void**)&wvh, g_wvh);
    cudaGetSymbolAddress((void**)&woh, g_woh);
    cudaGetSymbolAddress((void**)&q,   g_q);
    cudaGetSymbolAddress((void**)&k,   g_k);
    cudaGetSymbolAddress((void**)&qh,  g_qh);
    cudaGetSymbolAddress((void**)&kh,  g_kh);
    cudaGetSymbolAddress((void**)&vh,  g_vh);
    cudaGetSymbolAddress((void**)&s,   g_s);
    cudaGetSymbolAddress((void**)&ph,  g_p);
    cudaGetSymbolAddress((void**)&yh,  g_yh);

    cudaFuncSetAttribute(gemm_h_q,      cudaFuncAttributeMaxDynamicSharedMemorySize, SMEM_NT);
    cudaFuncSetAttribute(gemm_h_kv,     cudaFuncAttributeMaxDynamicSharedMemorySize, SMEM_NT);
    cudaFuncSetAttribute(gemm_h_o,      cudaFuncAttributeMaxDynamicSharedMemorySize, SMEM_NT);
    cudaFuncSetAttribute(gemm_h_scores, cudaFuncAttributeMaxDynamicSharedMemorySize, SMEM_NT);
    cudaFuncSetAttribute(gemm_h_av,     cudaFuncAttributeMaxDynamicSharedMemorySize, SMEM_AV);

    dim3 gblk(GTHREADS);

    // fp32 -> fp16 pre-converts
    {
        int n;
        n = T_SEQ * D_MODEL / 4;   cvt16<<<(n + 255) / 256, 256>>>(x,  xh,  n);
        n = D_MODEL * D_MODEL / 4; cvt16<<<(n + 255) / 256, 256>>>(wq, wqh, n);
        n = KV_DIM * D_MODEL / 4;  cvt16<<<(n + 255) / 256, 256>>>(wk, wkh, n);
        n = KV_DIM * D_MODEL / 4;  cvt16<<<(n + 255) / 256, 256>>>(wv, wvh, n);
        n = D_MODEL * D_MODEL / 4; cvt16<<<(n + 255) / 256, 256>>>(wo, woh, n);
    }

    gemm_h_q<<<dim3(D_MODEL / 256, T_SEQ / 128), gblk, SMEM_NT>>>(xh, wqh, q);
    gemm_h_kv<<<dim3(KV_DIM / 256, T_SEQ / 128, 2), gblk, SMEM_NT>>>(xh, wkh, wvh, k, vh);

    {
        int total = T_SEQ * (D_MODEL / 2) + T_SEQ * (KV_DIM / 2);
        rope_h<<<(total + 255) / 256, 256>>>(q, k, qh, kh, cosp, sinp);
    }

    const float scale = 0.08838834764831845f;   // 1/sqrt(128)
    gemm_h_scores<<<dim3(T_SEQ / 256, T_SEQ / 128, N_HEADS), gblk, SMEM_NT>>>(qh, kh, s, scale);
    softmax_p<<<N_HEADS * T_SEQ, 256>>>(s, ph);
    gemm_h_av<<<dim3(1, T_SEQ / 256, N_HEADS), gblk, SMEM_AV>>>(ph, vh, yh);

    gemm_h_o<<<dim3(D_MODEL / 256, T_SEQ / 128), gblk, SMEM_NT>>>(yh, woh, out);
}

// round 11
// speedup vs baseline: 1.5977x; 1.3053x over previous
#include <cuda_runtime.h>
#include <cuda_fp16.h>
#include <stdint.h>
#include <math.h>

// ---------------------------------------------------------------------------
// Problem constants (B=1)
// ---------------------------------------------------------------------------
#define T_SEQ 2048
#define D_MODEL 4096
#define KV_DIM 1024
#define HEAD_DIM 128
#define N_HEADS 32

#define BK 32
#define ROWB 80                 // bytes per fp16 smem row (32 halves + pad)
#define GTHREADS 512            // projection GEMMs: 16 warps
#define STG 30720               // (128+256) rows * 80 B
#define SMEM_NT (4 * STG)       // 122880

// Flash attention
#define FL_THREADS 256          // 8 warps, 16 q-rows each
#define FROW 272                // 128 halves + 16B pad
#define QBYTES (128 * FROW)     // 34816
#define KVST (2 * 128 * FROW)   // K tile + V tile per stage = 69632
#define SMEM_FL (QBYTES + 2 * KVST)   // 174080

// ---------------------------------------------------------------------------
// Scratch
// ---------------------------------------------------------------------------
__device__ __half g_xh[T_SEQ * D_MODEL];
__device__ __half g_wqh[D_MODEL * D_MODEL];
__device__ __half g_wkh[KV_DIM * D_MODEL];
__device__ __half g_wvh[KV_DIM * D_MODEL];
__device__ __half g_woh[D_MODEL * D_MODEL];
__device__ float  g_q[T_SEQ * D_MODEL];        // pre-rope fp32
__device__ float  g_k[T_SEQ * KV_DIM];
__device__ __half g_qh[T_SEQ * D_MODEL];
__device__ __half g_kh[T_SEQ * KV_DIM];
__device__ __half g_vh[T_SEQ * KV_DIM];
__device__ __half g_yh[T_SEQ * D_MODEL];

// ---------------------------------------------------------------------------
// Helpers
// ---------------------------------------------------------------------------
__device__ __forceinline__ uint32_t smem_u32(const void* p) {
    uint32_t a;
    asm("{ .reg .u64 t; cvta.to.shared.u64 t, %1; cvt.u32.u64 %0, t; }"
        : "=r"(a) : "l"(p));
    return a;
}

__device__ __forceinline__ void cp16(uint32_t dst, const void* src) {
    asm volatile("cp.async.cg.shared.global [%0], [%1], 16;" :: "r"(dst), "l"(src));
}
#define CP_COMMIT() asm volatile("cp.async.commit_group;" ::: "memory")
#define CP_WAIT(n)  asm volatile("cp.async.wait_group %0;" :: "n"(n) : "memory")

__device__ __forceinline__ uint32_t pk(float lo, float hi) {
    uint32_t r;
    asm("cvt.rn.f16x2.f32 %0, %1, %2;" : "=r"(r) : "f"(hi), "f"(lo));
    return r;
}

__device__ __forceinline__ void ldsm4(uint32_t& r0, uint32_t& r1, uint32_t& r2,
                                      uint32_t& r3, uint32_t a) {
    asm volatile("ldmatrix.sync.aligned.m8n8.x4.shared.b16 {%0,%1,%2,%3}, [%4];"
                 : "=r"(r0), "=r"(r1), "=r"(r2), "=r"(r3) : "r"(a));
}
__device__ __forceinline__ void ldsm4t(uint32_t& r0, uint32_t& r1, uint32_t& r2,
                                       uint32_t& r3, uint32_t a) {
    asm volatile("ldmatrix.sync.aligned.m8n8.x4.trans.shared.b16 {%0,%1,%2,%3}, [%4];"
                 : "=r"(r0), "=r"(r1), "=r"(r2), "=r"(r3) : "r"(a));
}

__device__ __forceinline__ void mma16816(float* d, uint32_t a0, uint32_t a1,
                                         uint32_t a2, uint32_t a3,
                                         uint32_t b0, uint32_t b1) {
    asm volatile(
        "mma.sync.aligned.m16n8k16.row.col.f32.f16.f16.f32 "
        "{%0,%1,%2,%3},{%4,%5,%6,%7},{%8,%9},{%0,%1,%2,%3};"
        : "+f"(d[0]), "+f"(d[1]), "+f"(d[2]), "+f"(d[3])
        : "r"(a0), "r"(a1), "r"(a2), "r"(a3), "r"(b0), "r"(b1));
}

// ---------------------------------------------------------------------------
// Projection GEMM machinery (R10, unchanged)
// ---------------------------------------------------------------------------
__device__ __forceinline__ void mma32x64(uint32_t sa, uint32_t sbb, int wm, int wn,
                                         int lane, float acc[2][8][4])
{
    const int sub = lane >> 3, rr = lane & 7;
    const uint32_t loff = ((sub & 1) * 8 + rr) * ROWB + (sub >> 1) * 16;
#pragma unroll
    for (int kk = 0; kk < 2; ++kk) {
        uint32_t a[2][4];
#pragma unroll
        for (int i = 0; i < 2; ++i)
            ldsm4(a[i][0], a[i][1], a[i][2], a[i][3],
                  sa + (wm * 32 + i * 16) * ROWB + kk * 32 + loff);
        uint32_t b[4][4];
#pragma unroll
        for (int jj = 0; jj < 4; ++jj)
            ldsm4(b[jj][0], b[jj][1], b[jj][2], b[jj][3],
                  sbb + (wn * 64 + jj * 16) * ROWB + kk * 32 + loff);
#pragma unroll
        for (int i = 0; i < 2; ++i)
#pragma unroll
            for (int jj = 0; jj < 4; ++jj) {
                mma16816(acc[i][jj * 2],     a[i][0], a[i][1], a[i][2], a[i][3],
                         b[jj][0], b[jj][2]);
                mma16816(acc[i][jj * 2 + 1], a[i][0], a[i][1], a[i][2], a[i][3],
                         b[jj][1], b[jj][3]);
            }
    }
}

template<bool HOUT>
__device__ __forceinline__ void store_acc32(void* Cv, int ldc,
                                            int row_base, int col_base,
                                            int wm, int wn, int lane,
                                            float acc[2][8][4], float scale)
{
    const int g = lane >> 2;
    const int t = lane & 3;
#pragma unroll
    for (int i = 0; i < 2; ++i) {
#pragma unroll
        for (int j = 0; j < 8; ++j) {
            int r = row_base + wm * 32 + i * 16 + g;
            int c = col_base + wn * 64 + j * 8 + t * 2;
            if (HOUT) {
                __half* C = (__half*)Cv;
                *(__half2*)(C + (size_t)r * ldc + c) =
                    __floats2half2_rn(acc[i][j][0] * scale, acc[i][j][1] * scale);
                *(__half2*)(C + (size_t)(r + 8) * ldc + c) =
                    __floats2half2_rn(acc[i][j][2] * scale, acc[i][j][3] * scale);
            } else {
                float* C = (float*)Cv;
                *(float2*)(C + (size_t)r * ldc + c) =
                    make_float2(acc[i][j][0] * scale, acc[i][j][1] * scale);
                *(float2*)(C + (size_t)(r + 8) * ldc + c) =
                    make_float2(acc[i][j][2] * scale, acc[i][j][3] * scale);
            }
        }
    }
}

__device__ __forceinline__ void stage_nt(uint32_t dst, const __half* __restrict__ A,
                                         int lda, const __half* __restrict__ B,
                                         int ldb, int k0, int tid)
{
#pragma unroll
    for (int it = 0; it < 3; ++it) {
        int c = tid + it * GTHREADS;
        int row = c >> 2;
        int kh = (c & 3) * 8;
        const __half* src = (row < 128)
            ? (A + (size_t)row * lda + k0 + kh)
            : (B + (size_t)(row - 128) * ldb + k0 + kh);
        cp16(dst + row * ROWB + (c & 3) * 16, src);
    }
}

template<bool HOUT>
__device__ __forceinline__ void gemm_core(const __half* Ab, const __half* Bb,
                                          void* C, int K, int lda, int ldb,
                                          int ldc, int row_base, int col_base,
                                          float scale, char* sm, int tid)
{
    const uint32_t sb = smem_u32(sm);
    const int lane = tid & 31, wid = tid >> 5;
    const int wm = wid & 3, wn = wid >> 2;

    float acc[2][8][4];
#pragma unroll
    for (int i = 0; i < 2; ++i)
#pragma unroll
        for (int j = 0; j < 8; ++j)
#pragma unroll
            for (int r = 0; r < 4; ++r) acc[i][j][r] = 0.f;

    const int NK = K / BK;

#pragma unroll
    for (int s = 0; s < 3; ++s) {
        stage_nt(sb + s * STG, Ab, lda, Bb, ldb, s * BK, tid);
        CP_COMMIT();
    }

    for (int kt = 0; kt < NK; ++kt) {
        CP_WAIT(2);
        __syncthreads();
        if (kt + 3 < NK)
            stage_nt(sb + ((kt + 3) & 3) * STG, Ab, lda, Bb, ldb, (kt + 3) * BK, tid);
        CP_COMMIT();
        const uint32_t s = sb + (kt & 3) * STG;
        mma32x64(s, s + 128 * ROWB, wm, wn, lane, acc);
    }
    store_acc32<HOUT>(C, ldc, row_base, col_base, wm, wn, lane, acc, scale);
}

__global__ __launch_bounds__(GTHREADS)
void gemm_h_q(const __half* __restrict__ X, const __half* __restrict__ W,
              float* __restrict__ C)
{
    extern __shared__ char sm[];
    gemm_core<false>(X + (size_t)blockIdx.y * 128 * D_MODEL,
                     W + (size_t)blockIdx.x * 256 * D_MODEL,
                     C, D_MODEL, D_MODEL, D_MODEL, D_MODEL,
                     blockIdx.y * 128, blockIdx.x * 256, 1.0f, sm, threadIdx.x);
}

__global__ __launch_bounds__(GTHREADS)
void gemm_h_kv(const __half* __restrict__ X,
               const __half* __restrict__ Wk, const __half* __restrict__ Wv,
               float* __restrict__ Ko, __half* __restrict__ Vo)
{
    extern __shared__ char sm[];
    const __half* Xb = X + (size_t)blockIdx.y * 128 * D_MODEL;
    if (blockIdx.z == 0)
        gemm_core<false>(Xb, Wk + (size_t)blockIdx.x * 256 * D_MODEL,
                         Ko, D_MODEL, D_MODEL, D_MODEL, KV_DIM,
                         blockIdx.y * 128, blockIdx.x * 256, 1.0f, sm, threadIdx.x);
    else
        gemm_core<true>(Xb, Wv + (size_t)blockIdx.x * 256 * D_MODEL,
                        Vo, D_MODEL, D_MODEL, D_MODEL, KV_DIM,
                        blockIdx.y * 128, blockIdx.x * 256, 1.0f, sm, threadIdx.x);
}

__global__ __launch_bounds__(GTHREADS)
void gemm_h_o(const __half* __restrict__ Y, const __half* __restrict__ W,
              float* __restrict__ C)
{
    extern __shared__ char sm[];
    gemm_core<false>(Y + (size_t)blockIdx.y * 128 * D_MODEL,
                     W + (size_t)blockIdx.x * 256 * D_MODEL,
                     C, D_MODEL, D_MODEL, D_MODEL, D_MODEL,
                     blockIdx.y * 128, blockIdx.x * 256, 1.0f, sm, threadIdx.x);
}

// ---------------------------------------------------------------------------
// Flash attention: one CTA = 128 q-rows of one head. 8 warps x 16 rows.
// Q frags in regs; K/V double-buffered cp.async; P stays in registers.
// ---------------------------------------------------------------------------
__device__ __forceinline__ void stage_kv(uint32_t dst, const __half* __restrict__ K,
                                         const __half* __restrict__ V,
                                         int kv0, int kvh, int tid)
{
#pragma unroll
    for (int it = 0; it < 8; ++it) {
        int c = tid + it * FL_THREADS;     // 0..2047
        int row = c >> 4, ch = c & 15;
        cp16(dst + row * FROW + ch * 16,
             K + (size_t)(kv0 + row) * KV_DIM + kvh * HEAD_DIM + ch * 8);
    }
#pragma unroll
    for (int it = 0; it < 8; ++it) {
        int c = tid + it * FL_THREADS;
        int row = c >> 4, ch = c & 15;
        cp16(dst + 128 * FROW + row * FROW + ch * 16,
             V + (size_t)(kv0 + row) * KV_DIM + kvh * HEAD_DIM + ch * 8);
    }
}

__global__ __launch_bounds__(FL_THREADS)
void flash_h(const __half* __restrict__ Q, const __half* __restrict__ K,
             const __half* __restrict__ V, __half* __restrict__ Y)
{
    extern __shared__ char sm[];
    const uint32_t sb = smem_u32(sm);
    const int h = blockIdx.y;
    const int qb = (int)(gridDim.x - 1 - blockIdx.x);   // heavy-first
    const int q0 = qb * 128;
    const int tid = threadIdx.x, lane = tid & 31, wq = tid >> 5;
    const int kvh = h >> 2;
    const int NB = qb + 1;

    // stage Q (once) + KV block 0 [+ KV block 1]
    {
#pragma unroll
        for (int it = 0; it < 8; ++it) {
            int c = tid + it * FL_THREADS;
            int row = c >> 4, ch = c & 15;
            cp16(sb + row * FROW + ch * 16,
                 Q + (size_t)(q0 + row) * D_MODEL + h * HEAD_DIM + ch * 8);
        }
        stage_kv(sb + QBYTES, K, V, 0, kvh, tid);
        CP_COMMIT();
    }
    if (NB > 1) {
        stage_kv(sb + QBYTES + KVST, K, V, 128, kvh, tid);
        CP_COMMIT();
        CP_WAIT(1);
    } else {
        CP_WAIT(0);
    }
    __syncthreads();

    const int sub = lane >> 3, rr = lane & 7;
    const uint32_t loff = ((sub & 1) * 8 + rr) * FROW + (sub >> 1) * 16;
    const int g = lane >> 2, t = lane & 3;
    const float scale = 0.08838834764831845f;

    // Q fragments (16 rows x 128 d), resident in registers
    uint32_t aq[8][4];
#pragma unroll
    for (int kc = 0; kc < 8; ++kc)
        ldsm4(aq[kc][0], aq[kc][1], aq[kc][2], aq[kc][3],
              sb + (wq * 16) * FROW + kc * 32 + loff);

    float m0 = -1e30f, m1 = -1e30f, l0 = 0.f, l1 = 0.f;
    float ao[16][4];
#pragma unroll
    for (int jt = 0; jt < 16; ++jt)
#pragma unroll
        for (int r = 0; r < 4; ++r) ao[jt][r] = 0.f;

    for (int kb = 0; kb < NB; ++kb) {
        const uint32_t kbase = sb + QBYTES + (kb & 1) * KVST;
        const uint32_t vbase = kbase + 128 * FROW;

        // ---- S = Q . K^T  (16 x 128) ----
        float sa[16][4];
#pragma unroll
        for (int jt = 0; jt < 16; ++jt)
#pragma unroll
            for (int r = 0; r < 4; ++r) sa[jt][r] = 0.f;
#pragma unroll
        for (int kc = 0; kc < 8; ++kc) {
#pragma unroll
            for (int nb = 0; nb < 8; ++nb) {
                uint32_t b0, b1, b2, b3;
                ldsm4(b0, b1, b2, b3, kbase + (nb * 16) * FROW + kc * 32 + loff);
                mma16816(sa[2 * nb],     aq[kc][0], aq[kc][1], aq[kc][2], aq[kc][3], b0, b2);
                mma16816(sa[2 * nb + 1], aq[kc][0], aq[kc][1], aq[kc][2], aq[kc][3], b1, b3);
            }
        }

        // ---- scale + causal mask ----
        const int rA = wq * 16 + g, rB = rA + 8;
        if (kb == qb) {
#pragma unroll
            for (int jt = 0; jt < 16; ++jt) {
                int c0 = jt * 8 + 2 * t, c1 = c0 + 1;
                sa[jt][0] = (c0 > rA) ? -1e30f : sa[jt][0] * scale;
                sa[jt][1] = (c1 > rA) ? -1e30f : sa[jt][1] * scale;
                sa[jt][2] = (c0 > rB) ? -1e30f : sa[jt][2] * scale;
                sa[jt][3] = (c1 > rB) ? -1e30f : sa[jt][3] * scale;
            }
        } else {
#pragma unroll
            for (int jt = 0; jt < 16; ++jt)
#pragma unroll
                for (int r = 0; r < 4; ++r) sa[jt][r] *= scale;
        }

        // ---- online softmax (rows rA, rB; reduce over lane bits 0,1) ----
        float mx0 = -1e30f, mx1 = -1e30f;
#pragma unroll
        for (int jt = 0; jt < 16; ++jt) {
            mx0 = fmaxf(mx0, fmaxf(sa[jt][0], sa[jt][1]));
            mx1 = fmaxf(mx1, fmaxf(sa[jt][2], sa[jt][3]));
        }
        mx0 = fmaxf(mx0, __shfl_xor_sync(0xffffffffu, mx0, 1));
        mx0 = fmaxf(mx0, __shfl_xor_sync(0xffffffffu, mx0, 2));
        mx1 = fmaxf(mx1, __shfl_xor_sync(0xffffffffu, mx1, 1));
        mx1 = fmaxf(mx1, __shfl_xor_sync(0xffffffffu, mx1, 2));

        const float mN0 = fmaxf(m0, mx0);
        const float mN1 = fmaxf(m1, mx1);
        const float al0 = __expf(m0 - mN0);
        const float al1 = __expf(m1 - mN1);

        float s0 = 0.f, s1 = 0.f;
#pragma unroll
        for (int jt = 0; jt < 16; ++jt) {
            float p0 = __expf(sa[jt][0] - mN0);
            float p1 = __expf(sa[jt][1] - mN0);
            float p2 = __expf(sa[jt][2] - mN1);
            float p3 = __expf(sa[jt][3] - mN1);
            sa[jt][0] = p0; sa[jt][1] = p1; sa[jt][2] = p2; sa[jt][3] = p3;
            s0 += p0 + p1; s1 += p2 + p3;
        }
        s0 += __shfl_xor_sync(0xffffffffu, s0, 1);
        s0 += __shfl_xor_sync(0xffffffffu, s0, 2);
        s1 += __shfl_xor_sync(0xffffffffu, s1, 1);
        s1 += __shfl_xor_sync(0xffffffffu, s1, 2);

        l0 = l0 * al0 + s0;  m0 = mN0;
        l1 = l1 * al1 + s1;  m1 = mN1;

#pragma unroll
        for (int jt = 0; jt < 16; ++jt) {
            ao[jt][0] *= al0; ao[jt][1] *= al0;
            ao[jt][2] *= al1; ao[jt][3] *= al1;
        }

        // ---- pack P into mma A fragments (C layout == A layout) ----
        uint32_t pa[8][4];
#pragma unroll
        for (int kc = 0; kc < 8; ++kc) {
            pa[kc][0] = pk(sa[2 * kc][0],     sa[2 * kc][1]);
            pa[kc][1] = pk(sa[2 * kc][2],     sa[2 * kc][3]);
            pa[kc][2] = pk(sa[2 * kc + 1][0], sa[2 * kc + 1][1]);
            pa[kc][3] = pk(sa[2 * kc + 1][2], sa[2 * kc + 1][3]);
        }

        // ---- O += P . V ----
#pragma unroll
        for (int kc = 0; kc < 8; ++kc) {
#pragma unroll
            for (int nb = 0; nb < 8; ++nb) {
                uint32_t b0, b1, b2, b3;
                ldsm4t(b0, b1, b2, b3,
                       vbase + (kc * 16 + (sub >> 1) * 8 + rr) * FROW
                             + (nb * 16) * 2 + (sub & 1) * 16);
                mma16816(ao[2 * nb],     pa[kc][0], pa[kc][1], pa[kc][2], pa[kc][3], b0, b2);
                mma16816(ao[2 * nb + 1], pa[kc][0], pa[kc][1], pa[kc][2], pa[kc][3], b1, b3);
            }
        }

        // ---- pipeline: prefetch kb+2 into the buffer just freed ----
        if (kb + 1 < NB) {
            __syncthreads();
            if (kb + 2 < NB) {
                stage_kv(sb + QBYTES + (kb & 1) * KVST, K, V, (kb + 2) * 128, kvh, tid);
                CP_COMMIT();
                CP_WAIT(1);
            } else {
                CP_WAIT(0);
            }
            __syncthreads();
        }
    }

    // ---- epilogue: O /= l, write fp16 y ----
    const float i0 = 1.f / l0, i1 = 1.f / l1;
    const int rowA = q0 + wq * 16 + g;
    __half* yr = Y + (size_t)rowA * D_MODEL + h * HEAD_DIM;
#pragma unroll
    for (int jt = 0; jt < 16; ++jt) {
        int col = jt * 8 + t * 2;
        *(__half2*)(yr + col) = __floats2half2_rn(ao[jt][0] * i0, ao[jt][1] * i0);
        *(__half2*)(yr + 8 * D_MODEL + col) = __floats2half2_rn(ao[jt][2] * i1, ao[jt][3] * i1);
    }
}

// ---------------------------------------------------------------------------
// RoPE: fp32 q,k -> rotate -> fp16 qh,kh
// ---------------------------------------------------------------------------
__global__ __launch_bounds__(256)
void rope_h(const float* __restrict__ q, const float* __restrict__ k,
            __half* __restrict__ qh, __half* __restrict__ kh,
            const float* __restrict__ cosp, const float* __restrict__ sinp)
{
    const int idx = blockIdx.x * blockDim.x + threadIdx.x;
    const int qpairs = T_SEQ * (D_MODEL / 2);
    const int kpairs = T_SEQ * (KV_DIM / 2);
    if (idx < qpairs) {
        int t = idx / (D_MODEL / 2);
        int p = idx % (D_MODEL / 2);
        int i = p & 63;
        float c = cosp[t * 64 + i];
        float s = sinp[t * 64 + i];
        const float* ptr = q + (size_t)t * D_MODEL + p * 2;
        float x1 = ptr[0], x2 = ptr[1];
        *(__half2*)(qh + (size_t)t * D_MODEL + p * 2) =
            __floats2half2_rn(x1 * c - x2 * s, x1 * s + x2 * c);
    } else if (idx < qpairs + kpairs) {
        int rI = idx - qpairs;
        int t = rI / (KV_DIM / 2);
        int p = rI % (KV_DIM / 2);
        int i = p & 63;
        float c = cosp[t * 64 + i];
        float s = sinp[t * 64 + i];
        const float* ptr = k + (size_t)t * KV_DIM + p * 2;
        float x1 = ptr[0], x2 = ptr[1];
        *(__half2*)(kh + (size_t)t * KV_DIM + p * 2) =
            __floats2half2_rn(x1 * c - x2 * s, x1 * s + x2 * c);
    }
}

// ---------------------------------------------------------------------------
// fp32 -> fp16 convert (vectorized)
// ---------------------------------------------------------------------------
__global__ __launch_bounds__(256)
void cvt16(const float* __restrict__ in, __half* __restrict__ out, int n4)
{
    int i = blockIdx.x * 256 + threadIdx.x;
    if (i < n4) {
        float4 v = ((const float4*)in)[i];
        ((__half2*)out)[i * 2]     = __floats2half2_rn(v.x, v.y);
        ((__half2*)out)[i * 2 + 1] = __floats2half2_rn(v.z, v.w);
    }
}

// ---------------------------------------------------------------------------
// Launch
// ---------------------------------------------------------------------------
extern "C" void kernel_launch(void* const* d_in, const int* in_sizes, int n_in,
                              void* d_out, int out_size)
{
    const float* x    = (const float*)d_in[0];
    const float* cosp = (const float*)d_in[1];
    const float* sinp = (const float*)d_in[2];
    const float* wq   = (const float*)d_in[3];
    const float* wk   = (const float*)d_in[4];
    const float* wv   = (const float*)d_in[5];
    const float* wo   = (const float*)d_in[6];
    float* out = (float*)d_out;

    __half *xh, *wqh, *wkh, *wvh, *woh, *qh, *kh, *vh, *yh;
    float *q, *k;
    cudaGetSymbolAddress((void**)&xh,  g_xh);
    cudaGetSymbolAddress((void**)&wqh, g_wqh);
    cudaGetSymbolAddress((void**)&wkh, g_wkh);
    cudaGetSymbolAddress((void**)&wvh, g_wvh);
    cudaGetSymbolAddress((void**)&woh, g_woh);
    cudaGetSymbolAddress((void**)&q,   g_q);
    cudaGetSymbolAddress((void**)&k,   g_k);
    cudaGetSymbolAddress((void**)&qh,  g_qh);
    cudaGetSymbolAddress((void**)&kh,  g_kh);
    cudaGetSymbolAddress((void**)&vh,  g_vh);
    cudaGetSymbolAddress((void**)&yh,  g_yh);

    cudaFuncSetAttribute(gemm_h_q,  cudaFuncAttributeMaxDynamicSharedMemorySize, SMEM_NT);
    cudaFuncSetAttribute(gemm_h_kv, cudaFuncAttributeMaxDynamicSharedMemorySize, SMEM_NT);
    cudaFuncSetAttribute(gemm_h_o,  cudaFuncAttributeMaxDynamicSharedMemorySize, SMEM_NT);
    cudaFuncSetAttribute(flash_h,   cudaFuncAttributeMaxDynamicSharedMemorySize, SMEM_FL);

    dim3 gblk(GTHREADS);

    // fp32 -> fp16 pre-converts
    {
        int n;
        n = T_SEQ * D_MODEL / 4;   cvt16<<<(n + 255) / 256, 256>>>(x,  xh,  n);
        n = D_MODEL * D_MODEL / 4; cvt16<<<(n + 255) / 256, 256>>>(wq, wqh, n);
        n = KV_DIM * D_MODEL / 4;  cvt16<<<(n + 255) / 256, 256>>>(wk, wkh, n);
        n = KV_DIM * D_MODEL / 4;  cvt16<<<(n + 255) / 256, 256>>>(wv, wvh, n);
        n = D_MODEL * D_MODEL / 4; cvt16<<<(n + 255) / 256, 256>>>(wo, woh, n);
    }

    gemm_h_q<<<dim3(D_MODEL / 256, T_SEQ / 128), gblk, SMEM_NT>>>(xh, wqh, q);
    gemm_h_kv<<<dim3(KV_DIM / 256, T_SEQ / 128, 2), gblk, SMEM_NT>>>(xh, wkh, wvh, k, vh);

    {
        int total = T_SEQ * (D_MODEL / 2) + T_SEQ * (KV_DIM / 2);
        rope_h<<<(total + 255) / 256, 256>>>(q, k, qh, kh, cosp, sinp);
    }

    flash_h<<<dim3(T_SEQ / 128, N_HEADS), dim3(FL_THREADS), SMEM_FL>>>(qh, kh, vh, yh);

    gemm_h_o<<<dim3(D_MODEL / 256, T_SEQ / 128), gblk, SMEM_NT>>>(yh, woh, out);
}

// round 12
// speedup vs baseline: 1.7104x; 1.0705x over previous
#include <cuda_runtime.h>
#include <cuda_fp16.h>
#include <stdint.h>
#include <math.h>

// ---------------------------------------------------------------------------
// Problem constants (B=1)
// ---------------------------------------------------------------------------
#define T_SEQ 2048
#define D_MODEL 4096
#define KV_DIM 1024
#define HEAD_DIM 128
#define N_HEADS 32

#define GTHREADS 512            // projection GEMMs: 16 warps
#define BK2 64
#define ROWB2 144               // 64 halves (128B) + 16B pad
#define STG2 55296              // 384 rows * 144 B
#define SMEM_NT2 (4 * STG2)     // 221184

// Flash attention
#define FL_THREADS 256          // 8 warps, 16 q-rows each
#define FROW 272                // 128 halves + 16B pad
#define QBYTES (128 * FROW)     // 34816
#define KVST (2 * 128 * FROW)   // K tile + V tile per stage = 69632
#define SMEM_FL (QBYTES + 2 * KVST)   // 174080

// ---------------------------------------------------------------------------
// Scratch
// ---------------------------------------------------------------------------
__device__ __half g_xh[T_SEQ * D_MODEL];
__device__ __half g_wqh[D_MODEL * D_MODEL];
__device__ __half g_wkh[KV_DIM * D_MODEL];
__device__ __half g_wvh[KV_DIM * D_MODEL];
__device__ __half g_woh[D_MODEL * D_MODEL];
__device__ __half g_qh[T_SEQ * D_MODEL];
__device__ __half g_kh[T_SEQ * KV_DIM];
__device__ __half g_vh[T_SEQ * KV_DIM];
__device__ __half g_yh[T_SEQ * D_MODEL];

// ---------------------------------------------------------------------------
// Helpers
// ---------------------------------------------------------------------------
__device__ __forceinline__ uint32_t smem_u32(const void* p) {
    uint32_t a;
    asm("{ .reg .u64 t; cvta.to.shared.u64 t, %1; cvt.u32.u64 %0, t; }"
        : "=r"(a) : "l"(p));
    return a;
}

__device__ __forceinline__ void cp16(uint32_t dst, const void* src) {
    asm volatile("cp.async.cg.shared.global [%0], [%1], 16;" :: "r"(dst), "l"(src));
}
#define CP_COMMIT() asm volatile("cp.async.commit_group;" ::: "memory")
#define CP_WAIT(n)  asm volatile("cp.async.wait_group %0;" :: "n"(n) : "memory")

__device__ __forceinline__ uint32_t pk(float lo, float hi) {
    uint32_t r;
    asm("cvt.rn.f16x2.f32 %0, %1, %2;" : "=r"(r) : "f"(hi), "f"(lo));
    return r;
}

__device__ __forceinline__ void ldsm4(uint32_t& r0, uint32_t& r1, uint32_t& r2,
                                      uint32_t& r3, uint32_t a) {
    asm volatile("ldmatrix.sync.aligned.m8n8.x4.shared.b16 {%0,%1,%2,%3}, [%4];"
                 : "=r"(r0), "=r"(r1), "=r"(r2), "=r"(r3) : "r"(a));
}
__device__ __forceinline__ void ldsm4t(uint32_t& r0, uint32_t& r1, uint32_t& r2,
                                       uint32_t& r3, uint32_t a) {
    asm volatile("ldmatrix.sync.aligned.m8n8.x4.trans.shared.b16 {%0,%1,%2,%3}, [%4];"
                 : "=r"(r0), "=r"(r1), "=r"(r2), "=r"(r3) : "r"(a));
}

__device__ __forceinline__ void mma16816(float* d, uint32_t a0, uint32_t a1,
                                         uint32_t a2, uint32_t a3,
                                         uint32_t b0, uint32_t b1) {
    asm volatile(
        "mma.sync.aligned.m16n8k16.row.col.f32.f16.f16.f32 "
        "{%0,%1,%2,%3},{%4,%5,%6,%7},{%8,%9},{%0,%1,%2,%3};"
        : "+f"(d[0]), "+f"(d[1]), "+f"(d[2]), "+f"(d[3])
        : "r"(a0), "r"(a1), "r"(a2), "r"(a3), "r"(b0), "r"(b1));
}

// ---------------------------------------------------------------------------
// Projection GEMM: CTA tile [128,256], BK=64, 4-stage cp.async ring, 16 warps
// ---------------------------------------------------------------------------
__device__ __forceinline__ void stage_nt64(uint32_t dst, const __half* __restrict__ A,
                                           int lda, const __half* __restrict__ B,
                                           int ldb, int k0, int tid)
{
#pragma unroll
    for (int it = 0; it < 6; ++it) {
        int c = tid + it * GTHREADS;          // 0..3071
        int row = c >> 3;                     // 0..383
        int ch = c & 7;                       // 16B chunk within 128B row
        const __half* src = (row < 128)
            ? (A + (size_t)row * lda + k0 + ch * 8)
            : (B + (size_t)(row - 128) * ldb + k0 + ch * 8);
        cp16(dst + row * ROWB2 + ch * 16, src);
    }
}

__device__ __forceinline__ void mma32x64_k64(uint32_t sa, uint32_t sbb, int wm, int wn,
                                             int lane, float acc[2][8][4])
{
    const int sub = lane >> 3, rr = lane & 7;
    const uint32_t loff = ((sub & 1) * 8 + rr) * ROWB2 + (sub >> 1) * 16;
#pragma unroll
    for (int kk = 0; kk < 4; ++kk) {
        uint32_t a[2][4];
#pragma unroll
        for (int i = 0; i < 2; ++i)
            ldsm4(a[i][0], a[i][1], a[i][2], a[i][3],
                  sa + (wm * 32 + i * 16) * ROWB2 + kk * 32 + loff);
        uint32_t b[4][4];
#pragma unroll
        for (int jj = 0; jj < 4; ++jj)
            ldsm4(b[jj][0], b[jj][1], b[jj][2], b[jj][3],
                  sbb + (wn * 64 + jj * 16) * ROWB2 + kk * 32 + loff);
#pragma unroll
        for (int i = 0; i < 2; ++i)
#pragma unroll
            for (int jj = 0; jj < 4; ++jj) {
                mma16816(acc[i][jj * 2],     a[i][0], a[i][1], a[i][2], a[i][3],
                         b[jj][0], b[jj][2]);
                mma16816(acc[i][jj * 2 + 1], a[i][0], a[i][1], a[i][2], a[i][3],
                         b[jj][1], b[jj][3]);
            }
    }
}

// MODE: 0 = fp32 out, 1 = fp16 out, 2 = fp16 out with fused RoPE
template<int MODE>
__device__ __forceinline__ void store_acc32(void* Cv, int ldc,
                                            int row_base, int col_base,
                                            int wm, int wn, int lane,
                                            float acc[2][8][4],
                                            const float* __restrict__ cosp,
                                            const float* __restrict__ sinp)
{
    const int g = lane >> 2;
    const int t = lane & 3;
#pragma unroll
    for (int i = 0; i < 2; ++i) {
#pragma unroll
        for (int j = 0; j < 8; ++j) {
            int r = row_base + wm * 32 + i * 16 + g;
            int c = col_base + wn * 64 + j * 8 + t * 2;
            if (MODE == 0) {
                float* C = (float*)Cv;
                *(float2*)(C + (size_t)r * ldc + c) =
                    make_float2(acc[i][j][0], acc[i][j][1]);
                *(float2*)(C + (size_t)(r + 8) * ldc + c) =
                    make_float2(acc[i][j][2], acc[i][j][3]);
            } else if (MODE == 1) {
                __half* C = (__half*)Cv;
                *(__half2*)(C + (size_t)r * ldc + c) =
                    __floats2half2_rn(acc[i][j][0], acc[i][j][1]);
                *(__half2*)(C + (size_t)(r + 8) * ldc + c) =
                    __floats2half2_rn(acc[i][j][2], acc[i][j][3]);
            } else {
                // fused RoPE: (c, c+1) is an interleaved pair within the head
                __half* C = (__half*)Cv;
                int p = (c & (HEAD_DIM - 1)) >> 1;
                float c0 = cosp[r * 64 + p],      s0 = sinp[r * 64 + p];
                float c1 = cosp[(r + 8) * 64 + p], s1 = sinp[(r + 8) * 64 + p];
                float x1 = acc[i][j][0], x2 = acc[i][j][1];
                *(__half2*)(C + (size_t)r * ldc + c) =
                    __floats2half2_rn(x1 * c0 - x2 * s0, x1 * s0 + x2 * c0);
                x1 = acc[i][j][2]; x2 = acc[i][j][3];
                *(__half2*)(C + (size_t)(r + 8) * ldc + c) =
                    __floats2half2_rn(x1 * c1 - x2 * s1, x1 * s1 + x2 * c1);
            }
        }
    }
}

template<int MODE>
__device__ __forceinline__ void gemm_core64(const __half* Ab, const __half* Bb,
                                            void* C, int K, int lda, int ldb,
                                            int ldc, int row_base, int col_base,
                                            const float* cosp, const float* sinp,
                                            char* sm, int tid)
{
    const uint32_t sb = smem_u32(sm);
    const int lane = tid & 31, wid = tid >> 5;
    const int wm = wid & 3, wn = wid >> 2;

    float acc[2][8][4];
#pragma unroll
    for (int i = 0; i < 2; ++i)
#pragma unroll
        for (int j = 0; j < 8; ++j)
#pragma unroll
            for (int r = 0; r < 4; ++r) acc[i][j][r] = 0.f;

    const int NK = K / BK2;

#pragma unroll
    for (int s = 0; s < 3; ++s) {
        stage_nt64(sb + s * STG2, Ab, lda, Bb, ldb, s * BK2, tid);
        CP_COMMIT();
    }

    for (int kt = 0; kt < NK; ++kt) {
        CP_WAIT(2);
        __syncthreads();
        if (kt + 3 < NK)
            stage_nt64(sb + ((kt + 3) & 3) * STG2, Ab, lda, Bb, ldb, (kt + 3) * BK2, tid);
        CP_COMMIT();
        const uint32_t s = sb + (kt & 3) * STG2;
        mma32x64_k64(s, s + 128 * ROWB2, wm, wn, lane, acc);
    }
    store_acc32<MODE>(C, ldc, row_base, col_base, wm, wn, lane, acc, cosp, sinp);
}

// q projection with fused RoPE -> fp16
__global__ __launch_bounds__(GTHREADS)
void gemm_h_q(const __half* __restrict__ X, const __half* __restrict__ W,
              __half* __restrict__ C,
              const float* __restrict__ cosp, const float* __restrict__ sinp)
{
    extern __shared__ char sm[];
    gemm_core64<2>(X + (size_t)blockIdx.y * 128 * D_MODEL,
                   W + (size_t)blockIdx.x * 256 * D_MODEL,
                   C, D_MODEL, D_MODEL, D_MODEL, D_MODEL,
                   blockIdx.y * 128, blockIdx.x * 256, cosp, sinp, sm, threadIdx.x);
}

// k (rope) and v (plain) projections
__global__ __launch_bounds__(GTHREADS)
void gemm_h_kv(const __half* __restrict__ X,
               const __half* __restrict__ Wk, const __half* __restrict__ Wv,
               __half* __restrict__ Ko, __half* __restrict__ Vo,
               const float* __restrict__ cosp, const float* __restrict__ sinp)
{
    extern __shared__ char sm[];
    const __half* Xb = X + (size_t)blockIdx.y * 128 * D_MODEL;
    if (blockIdx.z == 0)
        gemm_core64<2>(Xb, Wk + (size_t)blockIdx.x * 256 * D_MODEL,
                       Ko, D_MODEL, D_MODEL, D_MODEL, KV_DIM,
                       blockIdx.y * 128, blockIdx.x * 256, cosp, sinp, sm, threadIdx.x);
    else
        gemm_core64<1>(Xb, Wv + (size_t)blockIdx.x * 256 * D_MODEL,
                       Vo, D_MODEL, D_MODEL, D_MODEL, KV_DIM,
                       blockIdx.y * 128, blockIdx.x * 256, nullptr, nullptr, sm, threadIdx.x);
}

__global__ __launch_bounds__(GTHREADS)
void gemm_h_o(const __half* __restrict__ Y, const __half* __restrict__ W,
              float* __restrict__ C)
{
    extern __shared__ char sm[];
    gemm_core64<0>(Y + (size_t)blockIdx.y * 128 * D_MODEL,
                   W + (size_t)blockIdx.x * 256 * D_MODEL,
                   C, D_MODEL, D_MODEL, D_MODEL, D_MODEL,
                   blockIdx.y * 128, blockIdx.x * 256, nullptr, nullptr, sm, threadIdx.x);
}

// ---------------------------------------------------------------------------
// Flash attention (R11, unchanged): one CTA = 128 q-rows of one head.
// ---------------------------------------------------------------------------
__device__ __forceinline__ void stage_kv(uint32_t dst, const __half* __restrict__ K,
                                         const __half* __restrict__ V,
                                         int kv0, int kvh, int tid)
{
#pragma unroll
    for (int it = 0; it < 8; ++it) {
        int c = tid + it * FL_THREADS;
        int row = c >> 4, ch = c & 15;
        cp16(dst + row * FROW + ch * 16,
             K + (size_t)(kv0 + row) * KV_DIM + kvh * HEAD_DIM + ch * 8);
    }
#pragma unroll
    for (int it = 0; it < 8; ++it) {
        int c = tid + it * FL_THREADS;
        int row = c >> 4, ch = c & 15;
        cp16(dst + 128 * FROW + row * FROW + ch * 16,
             V + (size_t)(kv0 + row) * KV_DIM + kvh * HEAD_DIM + ch * 8);
    }
}

__global__ __launch_bounds__(FL_THREADS)
void flash_h(const __half* __restrict__ Q, const __half* __restrict__ K,
             const __half* __restrict__ V, __half* __restrict__ Y)
{
    extern __shared__ char sm[];
    const uint32_t sb = smem_u32(sm);
    const int h = blockIdx.y;
    const int qb = (int)(gridDim.x - 1 - blockIdx.x);   // heavy-first
    const int q0 = qb * 128;
    const int tid = threadIdx.x, lane = tid & 31, wq = tid >> 5;
    const int kvh = h >> 2;
    const int NB = qb + 1;

    {
#pragma unroll
        for (int it = 0; it < 8; ++it) {
            int c = tid + it * FL_THREADS;
            int row = c >> 4, ch = c & 15;
            cp16(sb + row * FROW + ch * 16,
                 Q + (size_t)(q0 + row) * D_MODEL + h * HEAD_DIM + ch * 8);
        }
        stage_kv(sb + QBYTES, K, V, 0, kvh, tid);
        CP_COMMIT();
    }
    if (NB > 1) {
        stage_kv(sb + QBYTES + KVST, K, V, 128, kvh, tid);
        CP_COMMIT();
        CP_WAIT(1);
    } else {
        CP_WAIT(0);
    }
    __syncthreads();

    const int sub = lane >> 3, rr = lane & 7;
    const uint32_t loff = ((sub & 1) * 8 + rr) * FROW + (sub >> 1) * 16;
    const int g = lane >> 2, t = lane & 3;
    const float scale = 0.08838834764831845f;

    uint32_t aq[8][4];
#pragma unroll
    for (int kc = 0; kc < 8; ++kc)
        ldsm4(aq[kc][0], aq[kc][1], aq[kc][2], aq[kc][3],
              sb + (wq * 16) * FROW + kc * 32 + loff);

    float m0 = -1e30f, m1 = -1e30f, l0 = 0.f, l1 = 0.f;
    float ao[16][4];
#pragma unroll
    for (int jt = 0; jt < 16; ++jt)
#pragma unroll
        for (int r = 0; r < 4; ++r) ao[jt][r] = 0.f;

    for (int kb = 0; kb < NB; ++kb) {
        const uint32_t kbase = sb + QBYTES + (kb & 1) * KVST;
        const uint32_t vbase = kbase + 128 * FROW;

        float sa[16][4];
#pragma unroll
        for (int jt = 0; jt < 16; ++jt)
#pragma unroll
            for (int r = 0; r < 4; ++r) sa[jt][r] = 0.f;
#pragma unroll
        for (int kc = 0; kc < 8; ++kc) {
#pragma unroll
            for (int nb = 0; nb < 8; ++nb) {
                uint32_t b0, b1, b2, b3;
                ldsm4(b0, b1, b2, b3, kbase + (nb * 16) * FROW + kc * 32 + loff);
                mma16816(sa[2 * nb],     aq[kc][0], aq[kc][1], aq[kc][2], aq[kc][3], b0, b2);
                mma16816(sa[2 * nb + 1], aq[kc][0], aq[kc][1], aq[kc][2], aq[kc][3], b1, b3);
            }
        }

        const int rA = wq * 16 + g, rB = rA + 8;
        if (kb == qb) {
#pragma unroll
            for (int jt = 0; jt < 16; ++jt) {
                int c0 = jt * 8 + 2 * t, c1 = c0 + 1;
                sa[jt][0] = (c0 > rA) ? -1e30f : sa[jt][0] * scale;
                sa[jt][1] = (c1 > rA) ? -1e30f : sa[jt][1] * scale;
                sa[jt][2] = (c0 > rB) ? -1e30f : sa[jt][2] * scale;
                sa[jt][3] = (c1 > rB) ? -1e30f : sa[jt][3] * scale;
            }
        } else {
#pragma unroll
            for (int jt = 0; jt < 16; ++jt)
#pragma unroll
                for (int r = 0; r < 4; ++r) sa[jt][r] *= scale;
        }

        float mx0 = -1e30f, mx1 = -1e30f;
#pragma unroll
        for (int jt = 0; jt < 16; ++jt) {
            mx0 = fmaxf(mx0, fmaxf(sa[jt][0], sa[jt][1]));
            mx1 = fmaxf(mx1, fmaxf(sa[jt][2], sa[jt][3]));
        }
        mx0 = fmaxf(mx0, __shfl_xor_sync(0xffffffffu, mx0, 1));
        mx0 = fmaxf(mx0, __shfl_xor_sync(0xffffffffu, mx0, 2));
        mx1 = fmaxf(mx1, __shfl_xor_sync(0xffffffffu, mx1, 1));
        mx1 = fmaxf(mx1, __shfl_xor_sync(0xffffffffu, mx1, 2));

        const float mN0 = fmaxf(m0, mx0);
        const float mN1 = fmaxf(m1, mx1);
        const float al0 = __expf(m0 - mN0);
        const float al1 = __expf(m1 - mN1);

        float s0 = 0.f, s1 = 0.f;
#pragma unroll
        for (int jt = 0; jt < 16; ++jt) {
            float p0 = __expf(sa[jt][0] - mN0);
            float p1 = __expf(sa[jt][1] - mN0);
            float p2 = __expf(sa[jt][2] - mN1);
            float p3 = __expf(sa[jt][3] - mN1);
            sa[jt][0] = p0; sa[jt][1] = p1; sa[jt][2] = p2; sa[jt][3] = p3;
            s0 += p0 + p1; s1 += p2 + p3;
        }
        s0 += __shfl_xor_sync(0xffffffffu, s0, 1);
        s0 += __shfl_xor_sync(0xffffffffu, s0, 2);
        s1 += __shfl_xor_sync(0xffffffffu, s1, 1);
        s1 += __shfl_xor_sync(0xffffffffu, s1, 2);

        l0 = l0 * al0 + s0;  m0 = mN0;
        l1 = l1 * al1 + s1;  m1 = mN1;

#pragma unroll
        for (int jt = 0; jt < 16; ++jt) {
            ao[jt][0] *= al0; ao[jt][1] *= al0;
            ao[jt][2] *= al1; ao[jt][3] *= al1;
        }

        uint32_t pa[8][4];
#pragma unroll
        for (int kc = 0; kc < 8; ++kc) {
            pa[kc][0] = pk(sa[2 * kc][0],     sa[2 * kc][1]);
            pa[kc][1] = pk(sa[2 * kc][2],     sa[2 * kc][3]);
            pa[kc][2] = pk(sa[2 * kc + 1][0], sa[2 * kc + 1][1]);
            pa[kc][3] = pk(sa[2 * kc + 1][2], sa[2 * kc + 1][3]);
        }

#pragma unroll
        for (int kc = 0; kc < 8; ++kc) {
#pragma unroll
            for (int nb = 0; nb < 8; ++nb) {
                uint32_t b0, b1, b2, b3;
                ldsm4t(b0, b1, b2, b3,
                       vbase + (kc * 16 + (sub >> 1) * 8 + rr) * FROW
                             + (nb * 16) * 2 + (sub & 1) * 16);
                mma16816(ao[2 * nb],     pa[kc][0], pa[kc][1], pa[kc][2], pa[kc][3], b0, b2);
                mma16816(ao[2 * nb + 1], pa[kc][0], pa[kc][1], pa[kc][2], pa[kc][3], b1, b3);
            }
        }

        if (kb + 1 < NB) {
            __syncthreads();
            if (kb + 2 < NB) {
                stage_kv(sb + QBYTES + (kb & 1) * KVST, K, V, (kb + 2) * 128, kvh, tid);
                CP_COMMIT();
                CP_WAIT(1);
            } else {
                CP_WAIT(0);
            }
            __syncthreads();
        }
    }

    const float i0 = 1.f / l0, i1 = 1.f / l1;
    const int rowA = q0 + wq * 16 + g;
    __half* yr = Y + (size_t)rowA * D_MODEL + h * HEAD_DIM;
#pragma unroll
    for (int jt = 0; jt < 16; ++jt) {
        int col = jt * 8 + t * 2;
        *(__half2*)(yr + col) = __floats2half2_rn(ao[jt][0] * i0, ao[jt][1] * i0);
        *(__half2*)(yr + 8 * D_MODEL + col) = __floats2half2_rn(ao[jt][2] * i1, ao[jt][3] * i1);
    }
}

// ---------------------------------------------------------------------------
// fp32 -> fp16 convert (vectorized)
// ---------------------------------------------------------------------------
__global__ __launch_bounds__(256)
void cvt16(const float* __restrict__ in, __half* __restrict__ out, int n4)
{
    int i = blockIdx.x * 256 + threadIdx.x;
    if (i < n4) {
        float4 v = ((const float4*)in)[i];
        ((__half2*)out)[i * 2]     = __floats2half2_rn(v.x, v.y);
        ((__half2*)out)[i * 2 + 1] = __floats2half2_rn(v.z, v.w);
    }
}

// ---------------------------------------------------------------------------
// Launch
// ---------------------------------------------------------------------------
extern "C" void kernel_launch(void* const* d_in, const int* in_sizes, int n_in,
                              void* d_out, int out_size)
{
    const float* x    = (const float*)d_in[0];
    const float* cosp = (const float*)d_in[1];
    const float* sinp = (const float*)d_in[2];
    const float* wq   = (const float*)d_in[3];
    const float* wk   = (const float*)d_in[4];
    const float* wv   = (const float*)d_in[5];
    const float* wo   = (const float*)d_in[6];
    float* out = (float*)d_out;

    __half *xh, *wqh, *wkh, *wvh, *woh, *qh, *kh, *vh, *yh;
    cudaGetSymbolAddress((void**)&xh,  g_xh);
    cudaGetSymbolAddress((void**)&wqh, g_wqh);
    cudaGetSymbolAddress((void**)&wkh, g_wkh);
    cudaGetSymbolAddress((void**)&wvh, g_wvh);
    cudaGetSymbolAddress((void**)&woh, g_woh);
    cudaGetSymbolAddress((void**)&qh,  g_qh);
    cudaGetSymbolAddress((void**)&kh,  g_kh);
    cudaGetSymbolAddress((void**)&vh,  g_vh);
    cudaGetSymbolAddress((void**)&yh,  g_yh);

    cudaFuncSetAttribute(gemm_h_q,  cudaFuncAttributeMaxDynamicSharedMemorySize, SMEM_NT2);
    cudaFuncSetAttribute(gemm_h_kv, cudaFuncAttributeMaxDynamicSharedMemorySize, SMEM_NT2);
    cudaFuncSetAttribute(gemm_h_o,  cudaFuncAttributeMaxDynamicSharedMemorySize, SMEM_NT2);
    cudaFuncSetAttribute(flash_h,   cudaFuncAttributeMaxDynamicSharedMemorySize, SMEM_FL);

    dim3 gblk(GTHREADS);

    // fp32 -> fp16 pre-converts
    {
        int n;
        n = T_SEQ * D_MODEL / 4;   cvt16<<<(n + 255) / 256, 256>>>(x,  xh,  n);
        n = D_MODEL * D_MODEL / 4; cvt16<<<(n + 255) / 256, 256>>>(wq, wqh, n);
        n = KV_DIM * D_MODEL / 4;  cvt16<<<(n + 255) / 256, 256>>>(wk, wkh, n);
        n = KV_DIM * D_MODEL / 4;  cvt16<<<(n + 255) / 256, 256>>>(wv, wvh, n);
        n = D_MODEL * D_MODEL / 4; cvt16<<<(n + 255) / 256, 256>>>(wo, woh, n);
    }

    gemm_h_q<<<dim3(D_MODEL / 256, T_SEQ / 128), gblk, SMEM_NT2>>>(xh, wqh, qh, cosp, sinp);
    gemm_h_kv<<<dim3(KV_DIM / 256, T_SEQ / 128, 2), gblk, SMEM_NT2>>>(
        xh, wkh, wvh, kh, vh, cosp, sinp);

    flash_h<<<dim3(T_SEQ / 128, N_HEADS), dim3(FL_THREADS), SMEM_FL>>>(qh, kh, vh, yh);

    gemm_h_o<<<dim3(D_MODEL / 256, T_SEQ / 128), gblk, SMEM_NT2>>>(yh, woh, out);
}